// round 12
// baseline (speedup 1.0000x reference)
#include <cuda_runtime.h>
#include <cuda_bf16.h>
#include <math.h>

#define B_ 16
#define N_ 1024
#define D_ 128
#define L_ 4
#define BN_ (B_*N_)
#define EMAX (1<<22)
#define SMEMZ 131072

typedef __nv_bfloat16 bf16;
typedef __nv_bfloat162 bf162;

__device__ __align__(128) float g_h [BN_*D_];
__device__ __align__(128) float g_hh[BN_*D_];
__device__ __align__(128) float g_hA[BN_*D_];
__device__ __align__(128) bf16  g_hhb[BN_*D_];
__device__ __align__(128) bf16  g_hAb[BN_*D_];
__device__ __align__(128) bf16  g_zb[4][BN_*D_];
__device__ __align__(128) float g_zA[BN_*D_];
__device__ __align__(128) float g_zC[BN_*D_];
__device__ __align__(128) float g_cf[2*BN_];
__device__ __align__(128) float g_pool[B_*D_];
__device__ __align__(128) int   g_rowptr[2][BN_ + 1];
__device__ __align__(128) int   g_us[2][BN_];
__device__ __align__(128) int   g_col[2][EMAX];
__device__ __align__(128) int   g_mir[2][EMAX];
__device__ __align__(128) float g_ev[2][EMAX];
__device__ __align__(128) float g_av[2][EMAX];
__device__ __align__(128) float g_invs[2*BN_];

// ---------- bf16 helpers ----------
__device__ __forceinline__ float4 ldz4(const bf16* p) {
    uint2 raw = *(const uint2*)p;
    bf162 lo = *reinterpret_cast<bf162*>(&raw.x);
    bf162 hi = *reinterpret_cast<bf162*>(&raw.y);
    float2 f0 = __bfloat1622float2(lo);
    float2 f1 = __bfloat1622float2(hi);
    return make_float4(f0.x, f0.y, f1.x, f1.y);
}
__device__ __forceinline__ void stz4(bf16* p, float4 v) {
    bf162 a = __floats2bfloat162_rn(v.x, v.y);
    bf162 b = __floats2bfloat162_rn(v.z, v.w);
    uint2 r;
    r.x = *reinterpret_cast<unsigned*>(&a);
    r.y = *reinterpret_cast<unsigned*>(&b);
    *(uint2*)p = r;
}

// ============ embede SGEMM: 64x128 tile, 4x8/thread (TRANSB) ============
__global__ void __launch_bounds__(256)
sgemm_e_k(const float* __restrict__ Ag, const float* __restrict__ Bg,
          float* __restrict__ Cg, int K)
{
    __shared__ float As[16][68];
    __shared__ float Bs[16][132];
    const int tid = threadIdx.x;
    const int tx = tid & 15, ty = tid >> 4;
    const int mbase = blockIdx.x * 64;

    const int arow  = tid >> 2;
    const int akoff = (tid & 3) * 4;
    const float* aptr = Ag + (size_t)(mbase + arow) * K + akoff;
    const int bn = tid & 127, bkh = (tid >> 7) * 8;
    const float* bptr = Bg + (size_t)bn * K + bkh;

    float acc[4][8];
#pragma unroll
    for (int i = 0; i < 4; i++)
#pragma unroll
        for (int j = 0; j < 8; j++) acc[i][j] = 0.f;

    const int nk = K >> 4;
    for (int kc = 0; kc < nk; ++kc) {
        float4 pa  = *(const float4*)(aptr + kc * 16);
        float4 pb0 = *(const float4*)(bptr + kc * 16);
        float4 pb1 = *(const float4*)(bptr + kc * 16 + 4);
        As[akoff+0][arow]=pa.x; As[akoff+1][arow]=pa.y;
        As[akoff+2][arow]=pa.z; As[akoff+3][arow]=pa.w;
        Bs[bkh+0][bn]=pb0.x; Bs[bkh+1][bn]=pb0.y;
        Bs[bkh+2][bn]=pb0.z; Bs[bkh+3][bn]=pb0.w;
        Bs[bkh+4][bn]=pb1.x; Bs[bkh+5][bn]=pb1.y;
        Bs[bkh+6][bn]=pb1.z; Bs[bkh+7][bn]=pb1.w;
        __syncthreads();
#pragma unroll
        for (int kk = 0; kk < 16; ++kk) {
            float4 av0 = *(const float4*)&As[kk][ty*4];
            float4 bv0 = *(const float4*)&Bs[kk][tx*8];
            float4 bv1 = *(const float4*)&Bs[kk][tx*8+4];
            float ar[4] = {av0.x,av0.y,av0.z,av0.w};
            float br[8] = {bv0.x,bv0.y,bv0.z,bv0.w,bv1.x,bv1.y,bv1.z,bv1.w};
#pragma unroll
            for (int i = 0; i < 4; i++)
#pragma unroll
                for (int j = 0; j < 8; j++)
                    acc[i][j] += ar[i] * br[j];
        }
        __syncthreads();
    }
    const int row0 = mbase + ty * 4;
    const int col0 = tx * 8;
#pragma unroll
    for (int i = 0; i < 4; i++) {
        float4* cp = (float4*)(Cg + (size_t)(row0 + i) * D_ + col0);
        cp[0] = make_float4(acc[i][0], acc[i][1], acc[i][2], acc[i][3]);
        cp[1] = make_float4(acc[i][4], acc[i][5], acc[i][6], acc[i][7]);
    }
}

// ===== fused: hh = h@W^T + b (f32+bf16), hA = hh@A (f32+bf16) ===
__global__ void __launch_bounds__(256)
hhA_k(const float* __restrict__ h, const float* __restrict__ W,
      const float* __restrict__ A, const float* __restrict__ bias,
      float* __restrict__ hh, bf16* __restrict__ hhb,
      float* __restrict__ hA, bf16* __restrict__ hAb)
{
    __shared__ float As[16][68];
    __shared__ float Bs[16][132];
    __shared__ float hhs[64][132];
    const int tid = threadIdx.x;
    const int tx = tid & 15, ty = tid >> 4;
    const int mbase = blockIdx.x * 64;

    const int arow  = tid >> 2;
    const int akoff = (tid & 3) * 4;
    const float* aptr = h + (size_t)(mbase + arow) * D_ + akoff;
    const int bn = tid & 127, bkh = (tid >> 7) * 8;
    const float* wptr = W + (size_t)bn * D_ + bkh;

    float acc[4][8];
#pragma unroll
    for (int i = 0; i < 4; i++)
#pragma unroll
        for (int j = 0; j < 8; j++) acc[i][j] = 0.f;

#pragma unroll 1
    for (int kc = 0; kc < 8; ++kc) {
        float4 pa  = *(const float4*)(aptr + kc * 16);
        float4 pb0 = *(const float4*)(wptr + kc * 16);
        float4 pb1 = *(const float4*)(wptr + kc * 16 + 4);
        As[akoff+0][arow]=pa.x; As[akoff+1][arow]=pa.y;
        As[akoff+2][arow]=pa.z; As[akoff+3][arow]=pa.w;
        Bs[bkh+0][bn]=pb0.x; Bs[bkh+1][bn]=pb0.y;
        Bs[bkh+2][bn]=pb0.z; Bs[bkh+3][bn]=pb0.w;
        Bs[bkh+4][bn]=pb1.x; Bs[bkh+5][bn]=pb1.y;
        Bs[bkh+6][bn]=pb1.z; Bs[bkh+7][bn]=pb1.w;
        __syncthreads();
#pragma unroll
        for (int kk = 0; kk < 16; ++kk) {
            float4 av0 = *(const float4*)&As[kk][ty*4];
            float4 bv0 = *(const float4*)&Bs[kk][tx*8];
            float4 bv1 = *(const float4*)&Bs[kk][tx*8+4];
            float ar[4] = {av0.x,av0.y,av0.z,av0.w};
            float br[8] = {bv0.x,bv0.y,bv0.z,bv0.w,bv1.x,bv1.y,bv1.z,bv1.w};
#pragma unroll
            for (int i = 0; i < 4; i++)
#pragma unroll
                for (int j = 0; j < 8; j++)
                    acc[i][j] += ar[i] * br[j];
        }
        __syncthreads();
    }

    const int row0 = ty * 4;
    const int col0 = tx * 8;
#pragma unroll
    for (int i = 0; i < 4; i++) {
        float o[8];
#pragma unroll
        for (int j = 0; j < 8; j++) {
            o[j] = acc[i][j] + bias[col0 + j];
            hhs[row0 + i][col0 + j] = o[j];
            acc[i][j] = 0.f;
        }
        const size_t go = (size_t)(mbase + row0 + i) * D_ + col0;
        *(float4*)(hh + go)     = make_float4(o[0], o[1], o[2], o[3]);
        *(float4*)(hh + go + 4) = make_float4(o[4], o[5], o[6], o[7]);
        stz4(hhb + go,     make_float4(o[0], o[1], o[2], o[3]));
        stz4(hhb + go + 4, make_float4(o[4], o[5], o[6], o[7]));
    }
    __syncthreads();

    const int bkr = tid >> 4, bcoff = (tid & 15) * 8;
#pragma unroll 1
    for (int kc = 0; kc < 8; ++kc) {
        const float* ap = A + (size_t)(kc * 16 + bkr) * D_ + bcoff;
        float4 pb0 = *(const float4*)ap;
        float4 pb1 = *(const float4*)(ap + 4);
        *(float4*)&Bs[bkr][bcoff]   = pb0;
        *(float4*)&Bs[bkr][bcoff+4] = pb1;
        __syncthreads();
#pragma unroll
        for (int kk = 0; kk < 16; ++kk) {
            float4 bv0 = *(const float4*)&Bs[kk][tx*8];
            float4 bv1 = *(const float4*)&Bs[kk][tx*8+4];
            float br[8] = {bv0.x,bv0.y,bv0.z,bv0.w,bv1.x,bv1.y,bv1.z,bv1.w};
#pragma unroll
            for (int i = 0; i < 4; i++) {
                const float a = hhs[row0 + i][kc * 16 + kk];
#pragma unroll
                for (int j = 0; j < 8; j++)
                    acc[i][j] += a * br[j];
            }
        }
        __syncthreads();
    }
#pragma unroll
    for (int i = 0; i < 4; i++) {
        const size_t go = (size_t)(mbase + row0 + i) * D_ + col0;
        *(float4*)(hA + go)     = make_float4(acc[i][0], acc[i][1], acc[i][2], acc[i][3]);
        *(float4*)(hA + go + 4) = make_float4(acc[i][4], acc[i][5], acc[i][6], acc[i][7]);
        stz4(hAb + go,     make_float4(acc[i][0], acc[i][1], acc[i][2], acc[i][3]));
        stz4(hAb + go + 4, make_float4(acc[i][4], acc[i][5], acc[i][6], acc[i][7]));
    }
}

// ============ CSR build (dual-adj via blockIdx.y) ============
__global__ void deg_k(const float* __restrict__ a0, const float* __restrict__ a1,
                      int* __restrict__ rp0, int* __restrict__ rp1)
{
    const float* adj = blockIdx.y ? a1 : a0;
    int* rp = blockIdx.y ? rp1 : rp0;
    const int wid = (blockIdx.x * blockDim.x + threadIdx.x) >> 5;
    const int lane = threadIdx.x & 31;
    if (wid >= BN_) return;
    const float* row = adj + (size_t)wid * N_;
    int c = 0;
#pragma unroll 4
    for (int k = 0; k < 32; k++) c += (row[lane + k * 32] > 0.f) ? 1 : 0;
    for (int o = 16; o; o >>= 1) c += __shfl_xor_sync(0xFFFFFFFFu, c, o);
    if (lane == 0) rp[wid + 1] = c;
}

__global__ void scan_k(int* __restrict__ rp0, int* __restrict__ rp1)
{
    int* rp = blockIdx.x ? rp1 : rp0;
    __shared__ int part[1024];
    const int t = threadIdx.x;
    int loc[16];
    int run = 0;
#pragma unroll
    for (int k = 0; k < 16; k++) { run += rp[1 + t * 16 + k]; loc[k] = run; }
    part[t] = run;
    __syncthreads();
    for (int off = 1; off < 1024; off <<= 1) {
        int v = (t >= off) ? part[t - off] : 0;
        __syncthreads();
        part[t] += v;
        __syncthreads();
    }
    const int excl = (t == 0) ? 0 : part[t - 1];
#pragma unroll
    for (int k = 0; k < 16; k++) rp[1 + t * 16 + k] = excl + loc[k];
    if (t == 0) rp[0] = 0;
}

__global__ void fill_k(const float* __restrict__ a0, const float* __restrict__ a1,
                       const int* __restrict__ rp0, const int* __restrict__ rp1,
                       int* __restrict__ col0, int* __restrict__ col1)
{
    const float* adj = blockIdx.y ? a1 : a0;
    const int* rp = blockIdx.y ? rp1 : rp0;
    int* col = blockIdx.y ? col1 : col0;
    const int wid = (blockIdx.x * blockDim.x + threadIdx.x) >> 5;
    const int lane = threadIdx.x & 31;
    if (wid >= BN_) return;
    const float* row = adj + (size_t)wid * N_;
    const int c0 = lane * 32;
    int cnt = 0;
#pragma unroll 4
    for (int k = 0; k < 32; k++) cnt += (row[c0 + k] > 0.f) ? 1 : 0;
    int inc = cnt;
    for (int off = 1; off < 32; off <<= 1) {
        int v = __shfl_up_sync(0xFFFFFFFFu, inc, off);
        if (lane >= off) inc += v;
    }
    int pos = rp[wid] + (inc - cnt);
    for (int k = 0; k < 32; k++)
        if (row[c0 + k] > 0.f) col[pos++] = c0 + k;
}

__global__ void mirror_k(const int* __restrict__ rp0, const int* __restrict__ col0,
                         int* __restrict__ mir0, int* __restrict__ us0,
                         const int* __restrict__ rp1, const int* __restrict__ col1,
                         int* __restrict__ mir1, int* __restrict__ us1)
{
    const int* rp  = blockIdx.y ? rp1  : rp0;
    const int* col = blockIdx.y ? col1 : col0;
    int* mir = blockIdx.y ? mir1 : mir0;
    int* us  = blockIdx.y ? us1  : us0;
    const int wid = (blockIdx.x * blockDim.x + threadIdx.x) >> 5;
    const int lane = threadIdx.x & 31;
    if (wid >= BN_) return;
    const int i = wid & (N_ - 1);
    const int bN = wid - i;
    const int rs = rp[wid], re = rp[wid + 1];
    for (int e = rs + lane; e < re; e += 32) {
        const int j = col[e];
        if (j == i) us[wid] = e;
        int lo = rp[bN + j], hi = rp[bN + j + 1];
        while (lo < hi) {
            int mid = (lo + hi) >> 1;
            if (col[mid] < i) lo = mid + 1; else hi = mid;
        }
        mir[e] = lo;
    }
}

// ===== edge logits: warp-per-row, 8-edge batches, bf16 j-gather ======
__global__ void __launch_bounds__(256)
elog2_k(const float* __restrict__ hh, const float* __restrict__ hA,
        const bf16* __restrict__ hhb, const bf16* __restrict__ hAb,
        const int* __restrict__ rp0, const int* __restrict__ col0,
        const int* __restrict__ mir0, const int* __restrict__ us0,
        float* __restrict__ ev0,
        const int* __restrict__ rp1, const int* __restrict__ col1,
        const int* __restrict__ mir1, const int* __restrict__ us1,
        float* __restrict__ ev1)
{
    const int br = blockIdx.y;
    const int* rp  = br ? rp1  : rp0;
    const int* col = br ? col1 : col0;
    const int* mir = br ? mir1 : mir0;
    const int* us  = br ? us1  : us0;
    float*     ev  = br ? ev1  : ev0;

    const int r = blockIdx.x * 8 + (threadIdx.x >> 5);
    const int lane = threadIdx.x & 31;
    const int bN = r & ~(N_ - 1);
    const size_t ro = (size_t)r * D_ + lane * 4;
    const float4 h1 = *(const float4*)(hh + ro);
    const float4 a1 = *(const float4*)(hA + ro);
    const int rs = us[r], re = rp[r + 1];

    for (int e0 = rs; e0 < re; e0 += 8) {
        const int cnt = min(8, re - e0);
        int jL = 0;
        if (lane < cnt) jL = col[e0 + lane];
        float v[8];
#pragma unroll
        for (int k = 0; k < 8; ++k) {
            const int j = __shfl_sync(0xFFFFFFFFu, jL, k);
            if (k < cnt) {
                const size_t jo = ((size_t)(bN + j)) * D_ + lane * 4;
                const float4 h2 = ldz4(hhb + jo);
                const float4 a2 = ldz4(hAb + jo);
                v[k] = a1.x*h2.x + a1.y*h2.y + a1.z*h2.z + a1.w*h2.w
                     + h1.x*a2.x + h1.y*a2.y + h1.z*a2.z + h1.w*a2.w;
            } else v[k] = 0.f;
        }
#pragma unroll
        for (int off = 16; off; off >>= 1) {
#pragma unroll
            for (int k = 0; k < 8; ++k)
                v[k] += __shfl_xor_sync(0xFFFFFFFFu, v[k], off);
        }
        // lane k stores edge k (static selection to avoid local-mem spill)
        float mine = v[0];
#pragma unroll
        for (int k = 1; k < 8; ++k)
            if (lane == k) mine = v[k];
        if (lane < cnt) {
            const float x = __expf(mine);
            const int e = e0 + lane;
            ev[e] = x;
            ev[mir[e]] = x;
        }
    }
}

// ===== softmax denominators, both branches =====
__global__ void stats2_k(const int* __restrict__ rp0, const float* __restrict__ ev0,
                         const int* __restrict__ rp1, const float* __restrict__ ev1,
                         float* __restrict__ invs)
{
    const int u = blockIdx.x * 8 + (threadIdx.x >> 5);
    const int lane = threadIdx.x & 31;
    if (u >= 2 * BN_) return;
    const bool s1 = (u >= BN_);
    const int r = s1 ? u - BN_ : u;
    const int* rp = s1 ? rp1 : rp0;
    const float* ev = s1 ? ev1 : ev0;
    const int rs = rp[r], re = rp[r + 1];
    float s = 0.f;
    for (int e = rs + lane; e < re; e += 32) s += ev[e];
    for (int o = 16; o; o >>= 1) s += __shfl_xor_sync(0xFFFFFFFFu, s, o);
    if (lane == 0) invs[u] = 1.f / (s + (float)(N_ - (re - rs)));
}

// ===== fold column normalizer, both branches =====
__global__ void fold2_k(const int* __restrict__ rp0, const int* __restrict__ col0,
                        const float* __restrict__ ev0, float* __restrict__ av0,
                        const int* __restrict__ rp1, const int* __restrict__ col1,
                        const float* __restrict__ ev1, float* __restrict__ av1,
                        const float* __restrict__ invs)
{
    const int u = blockIdx.x * 8 + (threadIdx.x >> 5);
    const int lane = threadIdx.x & 31;
    if (u >= 2 * BN_) return;
    const bool s1 = (u >= BN_);
    const int r = s1 ? u - BN_ : u;
    const int* rp  = s1 ? rp1  : rp0;
    const int* col = s1 ? col1 : col0;
    const float* ev = s1 ? ev1 : ev0;
    float* av = s1 ? av1 : av0;
    const int ibase = (s1 ? BN_ : 0) + (r & ~(N_ - 1));
    const int rs = rp[r], re = rp[r + 1];
    for (int e = rs + lane; e < re; e += 32)
        av[e] = ev[e] * invs[ibase + col[e]];
}

// ============ smem-tiled SpMM ============
// Block: one (graph b, branch br, dim-chunk dc, row-half rb).
// Stages z[b][:, dc*64:dc*64+64] (bf16, 128 KB) into smem; warps stream rows.
// EPI 0: store relu(acc) bf16 (az). EPI 1: c*hh+(1-c)*relu(acc) -> bf16.
// EPI 2: same -> fp32 (last hop).
template<int EPI>
__global__ void __launch_bounds__(256)
spmmT_k(const int* __restrict__ rp0, const int* __restrict__ col0,
        const float* __restrict__ av0,
        const int* __restrict__ rp1, const int* __restrict__ col1,
        const float* __restrict__ av1,
        const bf16* __restrict__ Z0, const bf16* __restrict__ Z1,
        bf16* __restrict__ outB0, bf16* __restrict__ outB1,
        float* __restrict__ outF0, float* __restrict__ outF1,
        const float* __restrict__ hh, const float* __restrict__ cf)
{
    extern __shared__ bf16 zs[];             // [1024][64]
    const int tid = threadIdx.x;
    const int b  = blockIdx.z & 15;
    const int br = blockIdx.z >> 4;
    const int dc = blockIdx.y;               // 0/1
    const int rb = blockIdx.x;               // 0/1
    const int* rp  = br ? rp1  : rp0;
    const int* col = br ? col1 : col0;
    const float* av= br ? av1  : av0;
    const bf16* Z  = (br ? Z1 : Z0) + (size_t)b * N_ * D_ + dc * 64;

    for (int q = tid; q < 8192; q += 256) {
        const int row = q >> 3, qd = q & 7;
        *(float4*)(zs + row * 64 + qd * 8) =
            *(const float4*)(Z + (size_t)row * D_ + qd * 8);
    }
    __syncthreads();

    const int warp = tid >> 5, lane = tid & 31;
    for (int rr = 0; rr < 64; ++rr) {
        const int i = rb * 512 + warp * 64 + rr;
        const int r = b * N_ + i;
        const int rs = rp[r], re = rp[r + 1];
        float ax = 0.f, ay = 0.f;
        for (int e0 = rs; e0 < re; e0 += 32) {
            const int cnt = min(32, re - e0);
            int jL = 0; float aL = 0.f;
            if (lane < cnt) { jL = col[e0 + lane]; aL = av[e0 + lane]; }
            for (int k = 0; k < cnt; ++k) {
                const int   j = __shfl_sync(0xFFFFFFFFu, jL, k);
                const float a = __shfl_sync(0xFFFFFFFFu, aL, k);
                const bf162 zv = *(const bf162*)(zs + j * 64 + lane * 2);
                const float2 f = __bfloat1622float2(zv);
                ax += a * f.x; ay += a * f.y;
            }
        }
        ax = fmaxf(ax, 0.f); ay = fmaxf(ay, 0.f);
        const size_t go = (size_t)r * D_ + dc * 64 + lane * 2;
        if (EPI == 0) {
            *(bf162*)((br ? outB1 : outB0) + go) = __floats2bfloat162_rn(ax, ay);
        } else {
            const float c = cf[br * BN_ + r], om = 1.f - c;
            const float2 hv = *(const float2*)(hh + go);
            const float ox = c * hv.x + om * ax;
            const float oy = c * hv.y + om * ay;
            if (EPI == 1)
                *(bf162*)((br ? outB1 : outB0) + go) = __floats2bfloat162_rn(ox, oy);
            else
                *(float2*)((br ? outF1 : outF0) + go) = make_float2(ox, oy);
        }
    }
}

// ===== gate + hop1 for both branches (az stored post-relu in az0/az1) =====
// NH1: h_out = (c1*hh+(1-c1)*az1) - (c0*hh+(1-c0)*az0)   [fp32]
// else: az0/az1 <- bf16(c*hh+(1-c)*az) in place; cf stored.
template<bool NH1>
__global__ void __launch_bounds__(256)
gatehop_k(const float* __restrict__ hh, bf16* __restrict__ az0,
          bf16* __restrict__ az1, const float* __restrict__ gw,
          const float* __restrict__ gb, float* __restrict__ cf,
          float* __restrict__ hout)
{
    const int r = blockIdx.x * 8 + (threadIdx.x >> 5);
    const int lane = threadIdx.x & 31;
    if (r >= BN_) return;
    const size_t o = (size_t)r * D_ + lane * 4;
    const float4 hv = *(const float4*)(hh + o);
    const float4 z0 = ldz4(az0 + o);
    const float4 z1 = ldz4(az1 + o);
    const float4 g1 = *(const float4*)(gw + lane * 4);
    const float4 g2 = *(const float4*)(gw + D_ + lane * 4);
    const float t = hv.x*g1.x + hv.y*g1.y + hv.z*g1.z + hv.w*g1.w;
    float s0 = t + z0.x*g2.x + z0.y*g2.y + z0.z*g2.z + z0.w*g2.w;
    float s1 = t + z1.x*g2.x + z1.y*g2.y + z1.z*g2.z + z1.w*g2.w;
#pragma unroll
    for (int off = 16; off; off >>= 1) {
        s0 += __shfl_xor_sync(0xFFFFFFFFu, s0, off);
        s1 += __shfl_xor_sync(0xFFFFFFFFu, s1, off);
    }
    const float gbv = gb[0];
    const float c0 = 1.f / (1.f + __expf(-(s0 + gbv)));
    const float c1 = 1.f / (1.f + __expf(-(s1 + gbv)));
    if (NH1) {
        float4 ov;
        ov.x = (c1*hv.x + (1.f-c1)*z1.x) - (c0*hv.x + (1.f-c0)*z0.x);
        ov.y = (c1*hv.y + (1.f-c1)*z1.y) - (c0*hv.y + (1.f-c0)*z0.y);
        ov.z = (c1*hv.z + (1.f-c1)*z1.z) - (c0*hv.z + (1.f-c0)*z0.z);
        ov.w = (c1*hv.w + (1.f-c1)*z1.w) - (c0*hv.w + (1.f-c0)*z0.w);
        *(float4*)(hout + o) = ov;
    } else {
        float4 w0, w1;
        w0.x = c0*hv.x + (1.f-c0)*z0.x; w0.y = c0*hv.y + (1.f-c0)*z0.y;
        w0.z = c0*hv.z + (1.f-c0)*z0.z; w0.w = c0*hv.w + (1.f-c0)*z0.w;
        w1.x = c1*hv.x + (1.f-c1)*z1.x; w1.y = c1*hv.y + (1.f-c1)*z1.y;
        w1.z = c1*hv.z + (1.f-c1)*z1.z; w1.w = c1*hv.w + (1.f-c1)*z1.w;
        stz4(az0 + o, w0);
        stz4(az1 + o, w1);
        if (lane == 0) { cf[r] = c0; cf[BN_ + r] = c1; }
    }
}

// ============ tail ============
__global__ void sub_k(const float* __restrict__ z2, const float* __restrict__ z1,
                      float* __restrict__ o)
{
    const size_t i = (size_t)blockIdx.x * blockDim.x + threadIdx.x;
    float4 a = ((const float4*)z2)[i];
    float4 b = ((const float4*)z1)[i];
    ((float4*)o)[i] = make_float4(a.x-b.x, a.y-b.y, a.z-b.z, a.w-b.w);
}

__global__ void pool_k(const float* __restrict__ h, const float* __restrict__ valid,
                       float* __restrict__ pooled)
{
    const int b = blockIdx.x, d = threadIdx.x;
    float s = 0.f, vs = 0.f;
#pragma unroll 8
    for (int n = 0; n < N_; n++) {
        float v = valid[b * N_ + n];
        s += h[((size_t)b * N_ + n) * D_ + d] * v;
        vs += v;
    }
    pooled[b * D_ + d] = s / vs;
}

__global__ void mlp_k(const float* __restrict__ pooled,
                      const float* __restrict__ w0, const float* __restrict__ b0,
                      const float* __restrict__ w1, const float* __restrict__ b1,
                      const float* __restrict__ w2, const float* __restrict__ b2,
                      const float* __restrict__ w3, const float* __restrict__ b3,
                      float* __restrict__ out)
{
    __shared__ float a0[128], a1[128], red[4];
    const int b = blockIdx.x, t = threadIdx.x;
    a0[t] = pooled[b * 128 + t];
    __syncthreads();
    float s = 0.f;
    for (int i = 0; i < 128; i++) s += a0[i] * w0[t*128+i];
    a1[t] = fmaxf(s + b0[t], 0.f);
    __syncthreads();
    s = 0.f;
    for (int i = 0; i < 128; i++) s += a1[i] * w1[t*128+i];
    a0[t] = fmaxf(s + b1[t], 0.f);
    __syncthreads();
    s = 0.f;
    for (int i = 0; i < 128; i++) s += a0[i] * w2[t*128+i];
    a1[t] = fmaxf(s + b2[t], 0.f);
    __syncthreads();
    float p = a1[t] * w3[t];
    for (int o = 16; o; o >>= 1) p += __shfl_xor_sync(0xFFFFFFFFu, p, o);
    if ((t & 31) == 0) red[t >> 5] = p;
    __syncthreads();
    if (t == 0) {
        float tot = red[0] + red[1] + red[2] + red[3] + b3[0];
        out[b] = 1.f / (1.f + expf(-tot));
    }
}

extern "C" void kernel_launch(void* const* d_in, const int* in_sizes, int n_in,
                              void* d_out, int out_size)
{
    const float* x       = (const float*)d_in[0];
    const float* adj1    = (const float*)d_in[1];
    const float* adj2    = (const float*)d_in[2];
    const float* valid   = (const float*)d_in[3];
    const float* embede_w= (const float*)d_in[4];
    const float* gW      = (const float*)d_in[5];
    const float* gb      = (const float*)d_in[6];
    const float* gA      = (const float*)d_in[7];
    const float* gate_w  = (const float*)d_in[8];
    const float* gate_b  = (const float*)d_in[9];
    const float* fc0_w   = (const float*)d_in[10];
    const float* fc0_b   = (const float*)d_in[11];
    const float* fc1_w   = (const float*)d_in[12];
    const float* fc1_b   = (const float*)d_in[13];
    const float* fc2_w   = (const float*)d_in[14];
    const float* fc2_b   = (const float*)d_in[15];
    const float* fc3_w   = (const float*)d_in[16];
    const float* fc3_b   = (const float*)d_in[17];
    float* out = (float*)d_out;

    float *p_h, *p_hh, *p_hA, *p_zA, *p_zC, *p_cf, *p_pool, *p_invs;
    bf16 *p_hhb, *p_hAb, *p_zb;
    float *p_ev, *p_av;
    int *p_rp, *p_col, *p_mir, *p_us;
    cudaGetSymbolAddress((void**)&p_h,   g_h);
    cudaGetSymbolAddress((void**)&p_hh,  g_hh);
    cudaGetSymbolAddress((void**)&p_hA,  g_hA);
    cudaGetSymbolAddress((void**)&p_hhb, g_hhb);
    cudaGetSymbolAddress((void**)&p_hAb, g_hAb);
    cudaGetSymbolAddress((void**)&p_zb,  g_zb);
    cudaGetSymbolAddress((void**)&p_zA,  g_zA);
    cudaGetSymbolAddress((void**)&p_zC,  g_zC);
    cudaGetSymbolAddress((void**)&p_cf,  g_cf);
    cudaGetSymbolAddress((void**)&p_pool,g_pool);
    cudaGetSymbolAddress((void**)&p_ev,  g_ev);
    cudaGetSymbolAddress((void**)&p_av,  g_av);
    cudaGetSymbolAddress((void**)&p_invs,g_invs);
    cudaGetSymbolAddress((void**)&p_rp,  g_rowptr);
    cudaGetSymbolAddress((void**)&p_col, g_col);
    cudaGetSymbolAddress((void**)&p_mir, g_mir);
    cudaGetSymbolAddress((void**)&p_us,  g_us);

    cudaFuncSetAttribute(spmmT_k<0>, cudaFuncAttributeMaxDynamicSharedMemorySize, SMEMZ);
    cudaFuncSetAttribute(spmmT_k<1>, cudaFuncAttributeMaxDynamicSharedMemorySize, SMEMZ);
    cudaFuncSetAttribute(spmmT_k<2>, cudaFuncAttributeMaxDynamicSharedMemorySize, SMEMZ);

    const int NHOPS[4] = {1, 2, 3, 4};
    int* rp_[2]   = {p_rp,  p_rp  + (BN_ + 1)};
    int* col_[2]  = {p_col, p_col + EMAX};
    int* mir_[2]  = {p_mir, p_mir + EMAX};
    int* us_[2]   = {p_us,  p_us  + BN_};
    float* ev_[2] = {p_ev,  p_ev  + EMAX};
    float* av_[2] = {p_av,  p_av  + EMAX};
    bf16* zb_[2][2] = {{p_zb,                    p_zb + (size_t)BN_*D_},
                       {p_zb + 2*(size_t)BN_*D_, p_zb + 3*(size_t)BN_*D_}};

    deg_k   <<<dim3(2048,2), 256>>>(adj1, adj2, rp_[0], rp_[1]);
    scan_k  <<<2, 1024>>>(rp_[0], rp_[1]);
    fill_k  <<<dim3(2048,2), 256>>>(adj1, adj2, rp_[0], rp_[1], col_[0], col_[1]);
    mirror_k<<<dim3(2048,2), 256>>>(rp_[0], col_[0], mir_[0], us_[0],
                                    rp_[1], col_[1], mir_[1], us_[1]);

    sgemm_e_k<<<256, 256>>>(x, embede_w, p_h, D_);

    const dim3 gT(2, 2, 32);
    for (int k = 0; k < L_; k++) {
        const float* Wk  = gW + (size_t)k * D_ * D_;
        const float* bk  = gb + (size_t)k * D_;
        const float* Ak  = gA + (size_t)k * D_ * D_;
        const float* gwk = gate_w + (size_t)k * 2 * D_;
        const float* gbk = gate_b + k;
        const int nhop = NHOPS[k];

        hhA_k<<<256, 256>>>(p_h, Wk, Ak, bk, p_hh, p_hhb, p_hA, p_hAb);

        elog2_k<<<dim3(2048, 2), 256>>>(p_hh, p_hA, p_hhb, p_hAb,
            rp_[0], col_[0], mir_[0], us_[0], ev_[0],
            rp_[1], col_[1], mir_[1], us_[1], ev_[1]);
        stats2_k<<<4096, 256>>>(rp_[0], ev_[0], rp_[1], ev_[1], p_invs);
        fold2_k <<<4096, 256>>>(rp_[0], col_[0], ev_[0], av_[0],
                                rp_[1], col_[1], ev_[1], av_[1], p_invs);

        // az = relu(att @ hh) for both branches
        spmmT_k<0><<<gT, 256, SMEMZ>>>(rp_[0], col_[0], av_[0],
            rp_[1], col_[1], av_[1], p_hhb, p_hhb,
            zb_[0][0], zb_[1][0], nullptr, nullptr, p_hh, p_cf);

        if (nhop == 1) {
            gatehop_k<true><<<2048, 256>>>(p_hh, zb_[0][0], zb_[1][0],
                                           gwk, gbk, p_cf, p_h);
        } else {
            gatehop_k<false><<<2048, 256>>>(p_hh, zb_[0][0], zb_[1][0],
                                            gwk, gbk, p_cf, nullptr);
            int cur = 0;
            for (int hp = 2; hp < nhop; hp++) {
                spmmT_k<1><<<gT, 256, SMEMZ>>>(rp_[0], col_[0], av_[0],
                    rp_[1], col_[1], av_[1], zb_[0][cur], zb_[1][cur],
                    zb_[0][cur^1], zb_[1][cur^1], nullptr, nullptr, p_hh, p_cf);
                cur ^= 1;
            }
            spmmT_k<2><<<gT, 256, SMEMZ>>>(rp_[0], col_[0], av_[0],
                rp_[1], col_[1], av_[1], zb_[0][cur], zb_[1][cur],
                nullptr, nullptr, p_zA, p_zC, p_hh, p_cf);
            sub_k<<<2048, 256>>>(p_zC, p_zA, p_h);
        }
    }

    pool_k<<<B_, D_>>>(p_h, valid, p_pool);
    mlp_k<<<B_, D_>>>(p_pool, fc0_w, fc0_b, fc1_w, fc1_b,
                      fc2_w, fc2_b, fc3_w, fc3_b, out);
}

// round 13
// speedup vs baseline: 1.5870x; 1.5870x over previous
#include <cuda_runtime.h>
#include <cuda_bf16.h>
#include <math.h>

#define B_ 16
#define N_ 1024
#define D_ 128
#define L_ 4
#define BN_ (B_*N_)
#define EMAX (1<<22)

typedef __nv_bfloat16 bf16;
typedef __nv_bfloat162 bf162;

__device__ __align__(128) float g_h [BN_*D_];
__device__ __align__(128) float g_hh[BN_*D_];
__device__ __align__(128) float g_hA[BN_*D_];
__device__ __align__(128) bf16  g_hhb[BN_*D_];
__device__ __align__(128) bf16  g_hAb[BN_*D_];
__device__ __align__(128) bf16  g_zb[4][BN_*D_];
__device__ __align__(128) float g_zA[BN_*D_];
__device__ __align__(128) float g_zC[BN_*D_];
__device__ __align__(128) float g_cf[2*BN_];
__device__ __align__(128) float g_pool[B_*D_];
__device__ __align__(128) int   g_rowptr[2][BN_ + 1];
__device__ __align__(128) int   g_us[2][BN_];
__device__ __align__(128) int   g_col[2][EMAX];
__device__ __align__(128) int   g_mir[2][EMAX];
__device__ __align__(128) float g_ev[2][EMAX];
__device__ __align__(128) float g_invs[2*BN_];

// ---------- bf16 helpers ----------
__device__ __forceinline__ float4 ldz4(const bf16* p) {
    uint2 raw = *(const uint2*)p;
    bf162 lo = *reinterpret_cast<bf162*>(&raw.x);
    bf162 hi = *reinterpret_cast<bf162*>(&raw.y);
    float2 f0 = __bfloat1622float2(lo);
    float2 f1 = __bfloat1622float2(hi);
    return make_float4(f0.x, f0.y, f1.x, f1.y);
}
__device__ __forceinline__ void stz4(bf16* p, float4 v) {
    bf162 a = __floats2bfloat162_rn(v.x, v.y);
    bf162 b = __floats2bfloat162_rn(v.z, v.w);
    uint2 r;
    r.x = *reinterpret_cast<unsigned*>(&a);
    r.y = *reinterpret_cast<unsigned*>(&b);
    *(uint2*)p = r;
}

// ============ embede SGEMM: 64x128 tile, 4x8/thread (TRANSB) ============
__global__ void __launch_bounds__(256)
sgemm_e_k(const float* __restrict__ Ag, const float* __restrict__ Bg,
          float* __restrict__ Cg, int K)
{
    __shared__ float As[16][68];
    __shared__ float Bs[16][132];
    const int tid = threadIdx.x;
    const int tx = tid & 15, ty = tid >> 4;
    const int mbase = blockIdx.x * 64;

    const int arow  = tid >> 2;
    const int akoff = (tid & 3) * 4;
    const float* aptr = Ag + (size_t)(mbase + arow) * K + akoff;
    const int bn = tid & 127, bkh = (tid >> 7) * 8;
    const float* bptr = Bg + (size_t)bn * K + bkh;

    float acc[4][8];
#pragma unroll
    for (int i = 0; i < 4; i++)
#pragma unroll
        for (int j = 0; j < 8; j++) acc[i][j] = 0.f;

    const int nk = K >> 4;
    for (int kc = 0; kc < nk; ++kc) {
        float4 pa  = *(const float4*)(aptr + kc * 16);
        float4 pb0 = *(const float4*)(bptr + kc * 16);
        float4 pb1 = *(const float4*)(bptr + kc * 16 + 4);
        As[akoff+0][arow]=pa.x; As[akoff+1][arow]=pa.y;
        As[akoff+2][arow]=pa.z; As[akoff+3][arow]=pa.w;
        Bs[bkh+0][bn]=pb0.x; Bs[bkh+1][bn]=pb0.y;
        Bs[bkh+2][bn]=pb0.z; Bs[bkh+3][bn]=pb0.w;
        Bs[bkh+4][bn]=pb1.x; Bs[bkh+5][bn]=pb1.y;
        Bs[bkh+6][bn]=pb1.z; Bs[bkh+7][bn]=pb1.w;
        __syncthreads();
#pragma unroll
        for (int kk = 0; kk < 16; ++kk) {
            float4 av0 = *(const float4*)&As[kk][ty*4];
            float4 bv0 = *(const float4*)&Bs[kk][tx*8];
            float4 bv1 = *(const float4*)&Bs[kk][tx*8+4];
            float ar[4] = {av0.x,av0.y,av0.z,av0.w};
            float br[8] = {bv0.x,bv0.y,bv0.z,bv0.w,bv1.x,bv1.y,bv1.z,bv1.w};
#pragma unroll
            for (int i = 0; i < 4; i++)
#pragma unroll
                for (int j = 0; j < 8; j++)
                    acc[i][j] += ar[i] * br[j];
        }
        __syncthreads();
    }
    const int row0 = mbase + ty * 4;
    const int col0 = tx * 8;
#pragma unroll
    for (int i = 0; i < 4; i++) {
        float4* cp = (float4*)(Cg + (size_t)(row0 + i) * D_ + col0);
        cp[0] = make_float4(acc[i][0], acc[i][1], acc[i][2], acc[i][3]);
        cp[1] = make_float4(acc[i][4], acc[i][5], acc[i][6], acc[i][7]);
    }
}

// ===== fused: hh = h@W^T + b (f32+bf16), hA = hh@A (f32+bf16) ===
__global__ void __launch_bounds__(256)
hhA_k(const float* __restrict__ h, const float* __restrict__ W,
      const float* __restrict__ A, const float* __restrict__ bias,
      float* __restrict__ hh, bf16* __restrict__ hhb,
      float* __restrict__ hA, bf16* __restrict__ hAb)
{
    __shared__ float As[16][68];
    __shared__ float Bs[16][132];
    __shared__ float hhs[64][132];
    const int tid = threadIdx.x;
    const int tx = tid & 15, ty = tid >> 4;
    const int mbase = blockIdx.x * 64;

    const int arow  = tid >> 2;
    const int akoff = (tid & 3) * 4;
    const float* aptr = h + (size_t)(mbase + arow) * D_ + akoff;
    const int bn = tid & 127, bkh = (tid >> 7) * 8;
    const float* wptr = W + (size_t)bn * D_ + bkh;

    float acc[4][8];
#pragma unroll
    for (int i = 0; i < 4; i++)
#pragma unroll
        for (int j = 0; j < 8; j++) acc[i][j] = 0.f;

#pragma unroll 1
    for (int kc = 0; kc < 8; ++kc) {
        float4 pa  = *(const float4*)(aptr + kc * 16);
        float4 pb0 = *(const float4*)(wptr + kc * 16);
        float4 pb1 = *(const float4*)(wptr + kc * 16 + 4);
        As[akoff+0][arow]=pa.x; As[akoff+1][arow]=pa.y;
        As[akoff+2][arow]=pa.z; As[akoff+3][arow]=pa.w;
        Bs[bkh+0][bn]=pb0.x; Bs[bkh+1][bn]=pb0.y;
        Bs[bkh+2][bn]=pb0.z; Bs[bkh+3][bn]=pb0.w;
        Bs[bkh+4][bn]=pb1.x; Bs[bkh+5][bn]=pb1.y;
        Bs[bkh+6][bn]=pb1.z; Bs[bkh+7][bn]=pb1.w;
        __syncthreads();
#pragma unroll
        for (int kk = 0; kk < 16; ++kk) {
            float4 av0 = *(const float4*)&As[kk][ty*4];
            float4 bv0 = *(const float4*)&Bs[kk][tx*8];
            float4 bv1 = *(const float4*)&Bs[kk][tx*8+4];
            float ar[4] = {av0.x,av0.y,av0.z,av0.w};
            float br[8] = {bv0.x,bv0.y,bv0.z,bv0.w,bv1.x,bv1.y,bv1.z,bv1.w};
#pragma unroll
            for (int i = 0; i < 4; i++)
#pragma unroll
                for (int j = 0; j < 8; j++)
                    acc[i][j] += ar[i] * br[j];
        }
        __syncthreads();
    }

    const int row0 = ty * 4;
    const int col0 = tx * 8;
#pragma unroll
    for (int i = 0; i < 4; i++) {
        float o[8];
#pragma unroll
        for (int j = 0; j < 8; j++) {
            o[j] = acc[i][j] + bias[col0 + j];
            hhs[row0 + i][col0 + j] = o[j];
            acc[i][j] = 0.f;
        }
        const size_t go = (size_t)(mbase + row0 + i) * D_ + col0;
        *(float4*)(hh + go)     = make_float4(o[0], o[1], o[2], o[3]);
        *(float4*)(hh + go + 4) = make_float4(o[4], o[5], o[6], o[7]);
        stz4(hhb + go,     make_float4(o[0], o[1], o[2], o[3]));
        stz4(hhb + go + 4, make_float4(o[4], o[5], o[6], o[7]));
    }
    __syncthreads();

    const int bkr = tid >> 4, bcoff = (tid & 15) * 8;
#pragma unroll 1
    for (int kc = 0; kc < 8; ++kc) {
        const float* ap = A + (size_t)(kc * 16 + bkr) * D_ + bcoff;
        float4 pb0 = *(const float4*)ap;
        float4 pb1 = *(const float4*)(ap + 4);
        *(float4*)&Bs[bkr][bcoff]   = pb0;
        *(float4*)&Bs[bkr][bcoff+4] = pb1;
        __syncthreads();
#pragma unroll
        for (int kk = 0; kk < 16; ++kk) {
            float4 bv0 = *(const float4*)&Bs[kk][tx*8];
            float4 bv1 = *(const float4*)&Bs[kk][tx*8+4];
            float br[8] = {bv0.x,bv0.y,bv0.z,bv0.w,bv1.x,bv1.y,bv1.z,bv1.w};
#pragma unroll
            for (int i = 0; i < 4; i++) {
                const float a = hhs[row0 + i][kc * 16 + kk];
#pragma unroll
                for (int j = 0; j < 8; j++)
                    acc[i][j] += a * br[j];
            }
        }
        __syncthreads();
    }
#pragma unroll
    for (int i = 0; i < 4; i++) {
        const size_t go = (size_t)(mbase + row0 + i) * D_ + col0;
        *(float4*)(hA + go)     = make_float4(acc[i][0], acc[i][1], acc[i][2], acc[i][3]);
        *(float4*)(hA + go + 4) = make_float4(acc[i][4], acc[i][5], acc[i][6], acc[i][7]);
        stz4(hAb + go,     make_float4(acc[i][0], acc[i][1], acc[i][2], acc[i][3]));
        stz4(hAb + go + 4, make_float4(acc[i][4], acc[i][5], acc[i][6], acc[i][7]));
    }
}

// ============ CSR build (dual-adj via blockIdx.y) ============
__global__ void deg_k(const float* __restrict__ a0, const float* __restrict__ a1,
                      int* __restrict__ rp0, int* __restrict__ rp1)
{
    const float* adj = blockIdx.y ? a1 : a0;
    int* rp = blockIdx.y ? rp1 : rp0;
    const int wid = (blockIdx.x * blockDim.x + threadIdx.x) >> 5;
    const int lane = threadIdx.x & 31;
    if (wid >= BN_) return;
    const float* row = adj + (size_t)wid * N_;
    int c = 0;
#pragma unroll 4
    for (int k = 0; k < 32; k++) c += (row[lane + k * 32] > 0.f) ? 1 : 0;
    for (int o = 16; o; o >>= 1) c += __shfl_xor_sync(0xFFFFFFFFu, c, o);
    if (lane == 0) rp[wid + 1] = c;
}

__global__ void scan_k(int* __restrict__ rp0, int* __restrict__ rp1)
{
    int* rp = blockIdx.x ? rp1 : rp0;
    __shared__ int part[1024];
    const int t = threadIdx.x;
    int loc[16];
    int run = 0;
#pragma unroll
    for (int k = 0; k < 16; k++) { run += rp[1 + t * 16 + k]; loc[k] = run; }
    part[t] = run;
    __syncthreads();
    for (int off = 1; off < 1024; off <<= 1) {
        int v = (t >= off) ? part[t - off] : 0;
        __syncthreads();
        part[t] += v;
        __syncthreads();
    }
    const int excl = (t == 0) ? 0 : part[t - 1];
#pragma unroll
    for (int k = 0; k < 16; k++) rp[1 + t * 16 + k] = excl + loc[k];
    if (t == 0) rp[0] = 0;
}

__global__ void fill_k(const float* __restrict__ a0, const float* __restrict__ a1,
                       const int* __restrict__ rp0, const int* __restrict__ rp1,
                       int* __restrict__ col0, int* __restrict__ col1)
{
    const float* adj = blockIdx.y ? a1 : a0;
    const int* rp = blockIdx.y ? rp1 : rp0;
    int* col = blockIdx.y ? col1 : col0;
    const int wid = (blockIdx.x * blockDim.x + threadIdx.x) >> 5;
    const int lane = threadIdx.x & 31;
    if (wid >= BN_) return;
    const float* row = adj + (size_t)wid * N_;
    const int c0 = lane * 32;
    int cnt = 0;
#pragma unroll 4
    for (int k = 0; k < 32; k++) cnt += (row[c0 + k] > 0.f) ? 1 : 0;
    int inc = cnt;
    for (int off = 1; off < 32; off <<= 1) {
        int v = __shfl_up_sync(0xFFFFFFFFu, inc, off);
        if (lane >= off) inc += v;
    }
    int pos = rp[wid] + (inc - cnt);
    for (int k = 0; k < 32; k++)
        if (row[c0 + k] > 0.f) col[pos++] = c0 + k;
}

__global__ void mirror_k(const int* __restrict__ rp0, const int* __restrict__ col0,
                         int* __restrict__ mir0, int* __restrict__ us0,
                         const int* __restrict__ rp1, const int* __restrict__ col1,
                         int* __restrict__ mir1, int* __restrict__ us1)
{
    const int* rp  = blockIdx.y ? rp1  : rp0;
    const int* col = blockIdx.y ? col1 : col0;
    int* mir = blockIdx.y ? mir1 : mir0;
    int* us  = blockIdx.y ? us1  : us0;
    const int wid = (blockIdx.x * blockDim.x + threadIdx.x) >> 5;
    const int lane = threadIdx.x & 31;
    if (wid >= BN_) return;
    const int i = wid & (N_ - 1);
    const int bN = wid - i;
    const int rs = rp[wid], re = rp[wid + 1];
    for (int e = rs + lane; e < re; e += 32) {
        const int j = col[e];
        if (j == i) us[wid] = e;
        int lo = rp[bN + j], hi = rp[bN + j + 1];
        while (lo < hi) {
            int mid = (lo + hi) >> 1;
            if (col[mid] < i) lo = mid + 1; else hi = mid;
        }
        mir[e] = lo;
    }
}

// ===== edge logits: warp-per-row, 8-edge batches, bf16 j-gather ======
__global__ void __launch_bounds__(256)
elog2_k(const float* __restrict__ hh, const float* __restrict__ hA,
        const bf16* __restrict__ hhb, const bf16* __restrict__ hAb,
        const int* __restrict__ rp0, const int* __restrict__ col0,
        const int* __restrict__ mir0, const int* __restrict__ us0,
        float* __restrict__ ev0,
        const int* __restrict__ rp1, const int* __restrict__ col1,
        const int* __restrict__ mir1, const int* __restrict__ us1,
        float* __restrict__ ev1)
{
    const int br = blockIdx.y;
    const int* rp  = br ? rp1  : rp0;
    const int* col = br ? col1 : col0;
    const int* mir = br ? mir1 : mir0;
    const int* us  = br ? us1  : us0;
    float*     ev  = br ? ev1  : ev0;

    const int r = blockIdx.x * 8 + (threadIdx.x >> 5);
    const int lane = threadIdx.x & 31;
    const int bN = r & ~(N_ - 1);
    const size_t ro = (size_t)r * D_ + lane * 4;
    const float4 h1 = *(const float4*)(hh + ro);
    const float4 a1 = *(const float4*)(hA + ro);
    const int rs = us[r], re = rp[r + 1];

    for (int e0 = rs; e0 < re; e0 += 8) {
        const int cnt = min(8, re - e0);
        int jL = 0;
        if (lane < cnt) jL = col[e0 + lane];
        float v[8];
#pragma unroll
        for (int k = 0; k < 8; ++k) {
            const int j = __shfl_sync(0xFFFFFFFFu, jL, k);
            if (k < cnt) {
                const size_t jo = ((size_t)(bN + j)) * D_ + lane * 4;
                const float4 h2 = ldz4(hhb + jo);
                const float4 a2 = ldz4(hAb + jo);
                v[k] = a1.x*h2.x + a1.y*h2.y + a1.z*h2.z + a1.w*h2.w
                     + h1.x*a2.x + h1.y*a2.y + h1.z*a2.z + h1.w*a2.w;
            } else v[k] = 0.f;
        }
#pragma unroll
        for (int off = 16; off; off >>= 1) {
#pragma unroll
            for (int k = 0; k < 8; ++k)
                v[k] += __shfl_xor_sync(0xFFFFFFFFu, v[k], off);
        }
        float mine = v[0];
#pragma unroll
        for (int k = 1; k < 8; ++k)
            if (lane == k) mine = v[k];
        if (lane < cnt) {
            const float x = __expf(mine);
            const int e = e0 + lane;
            ev[e] = x;
            ev[mir[e]] = x;
        }
    }
}

// ===== softmax denominators, both branches =====
__global__ void stats2_k(const int* __restrict__ rp0, const float* __restrict__ ev0,
                         const int* __restrict__ rp1, const float* __restrict__ ev1,
                         float* __restrict__ invs)
{
    const int u = blockIdx.x * 8 + (threadIdx.x >> 5);
    const int lane = threadIdx.x & 31;
    if (u >= 2 * BN_) return;
    const bool s1 = (u >= BN_);
    const int r = s1 ? u - BN_ : u;
    const int* rp = s1 ? rp1 : rp0;
    const float* ev = s1 ? ev1 : ev0;
    const int rs = rp[r], re = rp[r + 1];
    float s = 0.f;
    for (int e = rs + lane; e < re; e += 32) s += ev[e];
    for (int o = 16; o; o >>= 1) s += __shfl_xor_sync(0xFFFFFFFFu, s, o);
    if (lane == 0) invs[u] = 1.f / (s + (float)(N_ - (re - rs)));
}

// ============ SpMM: warp-per-row bf16 L2 gather, inline fold ============
// EPI 0: store relu(acc) -> bf16 (az).  EPI 1: c*hh+(1-c)*relu -> bf16.
// EPI 2: c*hh+(1-c)*relu -> fp32.
template<int EPI>
__global__ void __launch_bounds__(256)
spmm_k(const int* __restrict__ rp0, const int* __restrict__ col0,
       const float* __restrict__ ev0,
       const int* __restrict__ rp1, const int* __restrict__ col1,
       const float* __restrict__ ev1,
       const float* __restrict__ invs,
       const bf16* __restrict__ Z0, const bf16* __restrict__ Z1,
       bf16* __restrict__ outB0, bf16* __restrict__ outB1,
       float* __restrict__ outF0, float* __restrict__ outF1,
       const float* __restrict__ hh, const float* __restrict__ cf)
{
    const int u = blockIdx.x * 8 + (threadIdx.x >> 5);
    const int lane = threadIdx.x & 31;
    const bool s1 = (u >= BN_);
    const int r = s1 ? u - BN_ : u;
    const int* rp  = s1 ? rp1  : rp0;
    const int* col = s1 ? col1 : col0;
    const float* ev = s1 ? ev1 : ev0;
    const float* iv = invs + (s1 ? BN_ : 0) + (r & ~(N_ - 1));
    const bf16* zb = (s1 ? Z1 : Z0) + (size_t)(r & ~(N_ - 1)) * D_;
    const int rs = rp[r], re = rp[r + 1];
    const int off = lane * 4;

    float4 acc = make_float4(0.f, 0.f, 0.f, 0.f);
    int e = rs;
    for (; e + 4 <= re; e += 4) {
        const int   j0 = col[e],   j1 = col[e+1], j2 = col[e+2], j3 = col[e+3];
        const float a0 = ev[e]   * iv[j0];
        const float a1 = ev[e+1] * iv[j1];
        const float a2 = ev[e+2] * iv[j2];
        const float a3 = ev[e+3] * iv[j3];
        const float4 z0 = ldz4(zb + (size_t)j0 * D_ + off);
        const float4 z1 = ldz4(zb + (size_t)j1 * D_ + off);
        const float4 z2 = ldz4(zb + (size_t)j2 * D_ + off);
        const float4 z3 = ldz4(zb + (size_t)j3 * D_ + off);
        acc.x += a0*z0.x + a1*z1.x + a2*z2.x + a3*z3.x;
        acc.y += a0*z0.y + a1*z1.y + a2*z2.y + a3*z3.y;
        acc.z += a0*z0.z + a1*z1.z + a2*z2.z + a3*z3.z;
        acc.w += a0*z0.w + a1*z1.w + a2*z2.w + a3*z3.w;
    }
    for (; e < re; ++e) {
        const int j = col[e];
        const float a = ev[e] * iv[j];
        const float4 zv = ldz4(zb + (size_t)j * D_ + off);
        acc.x += a*zv.x; acc.y += a*zv.y; acc.z += a*zv.z; acc.w += a*zv.w;
    }

    acc.x = fmaxf(acc.x, 0.f); acc.y = fmaxf(acc.y, 0.f);
    acc.z = fmaxf(acc.z, 0.f); acc.w = fmaxf(acc.w, 0.f);
    const size_t go = (size_t)r * D_ + off;

    if (EPI == 0) {
        stz4((s1 ? outB1 : outB0) + go, acc);
    } else {
        const float c = cf[u], om = 1.f - c;
        const float4 hv = *(const float4*)(hh + go);
        float4 o;
        o.x = c*hv.x + om*acc.x; o.y = c*hv.y + om*acc.y;
        o.z = c*hv.z + om*acc.z; o.w = c*hv.w + om*acc.w;
        if (EPI == 1) stz4((s1 ? outB1 : outB0) + go, o);
        else          *(float4*)((s1 ? outF1 : outF0) + go) = o;
    }
}

// ===== gate + hop1 for both branches (az post-relu in az0/az1) =====
// NH1: h_out = (c1*hh+(1-c1)*az1) - (c0*hh+(1-c0)*az0)   [fp32]
// else: az0/az1 <- bf16(c*hh+(1-c)*az) in place; cf stored.
template<bool NH1>
__global__ void __launch_bounds__(256)
gatehop_k(const float* __restrict__ hh, bf16* __restrict__ az0,
          bf16* __restrict__ az1, const float* __restrict__ gw,
          const float* __restrict__ gb, float* __restrict__ cf,
          float* __restrict__ hout)
{
    const int r = blockIdx.x * 8 + (threadIdx.x >> 5);
    const int lane = threadIdx.x & 31;
    if (r >= BN_) return;
    const size_t o = (size_t)r * D_ + lane * 4;
    const float4 hv = *(const float4*)(hh + o);
    const float4 z0 = ldz4(az0 + o);
    const float4 z1 = ldz4(az1 + o);
    const float4 g1 = *(const float4*)(gw + lane * 4);
    const float4 g2 = *(const float4*)(gw + D_ + lane * 4);
    const float t = hv.x*g1.x + hv.y*g1.y + hv.z*g1.z + hv.w*g1.w;
    float s0 = t + z0.x*g2.x + z0.y*g2.y + z0.z*g2.z + z0.w*g2.w;
    float s1 = t + z1.x*g2.x + z1.y*g2.y + z1.z*g2.z + z1.w*g2.w;
#pragma unroll
    for (int off = 16; off; off >>= 1) {
        s0 += __shfl_xor_sync(0xFFFFFFFFu, s0, off);
        s1 += __shfl_xor_sync(0xFFFFFFFFu, s1, off);
    }
    const float gbv = gb[0];
    const float c0 = 1.f / (1.f + __expf(-(s0 + gbv)));
    const float c1 = 1.f / (1.f + __expf(-(s1 + gbv)));
    if (NH1) {
        float4 ov;
        ov.x = (c1*hv.x + (1.f-c1)*z1.x) - (c0*hv.x + (1.f-c0)*z0.x);
        ov.y = (c1*hv.y + (1.f-c1)*z1.y) - (c0*hv.y + (1.f-c0)*z0.y);
        ov.z = (c1*hv.z + (1.f-c1)*z1.z) - (c0*hv.z + (1.f-c0)*z0.z);
        ov.w = (c1*hv.w + (1.f-c1)*z1.w) - (c0*hv.w + (1.f-c0)*z0.w);
        *(float4*)(hout + o) = ov;
    } else {
        float4 w0, w1;
        w0.x = c0*hv.x + (1.f-c0)*z0.x; w0.y = c0*hv.y + (1.f-c0)*z0.y;
        w0.z = c0*hv.z + (1.f-c0)*z0.z; w0.w = c0*hv.w + (1.f-c0)*z0.w;
        w1.x = c1*hv.x + (1.f-c1)*z1.x; w1.y = c1*hv.y + (1.f-c1)*z1.y;
        w1.z = c1*hv.z + (1.f-c1)*z1.z; w1.w = c1*hv.w + (1.f-c1)*z1.w;
        stz4(az0 + o, w0);
        stz4(az1 + o, w1);
        if (lane == 0) { cf[r] = c0; cf[BN_ + r] = c1; }
    }
}

// ============ tail ============
__global__ void sub_k(const float* __restrict__ z2, const float* __restrict__ z1,
                      float* __restrict__ o)
{
    const size_t i = (size_t)blockIdx.x * blockDim.x + threadIdx.x;
    float4 a = ((const float4*)z2)[i];
    float4 b = ((const float4*)z1)[i];
    ((float4*)o)[i] = make_float4(a.x-b.x, a.y-b.y, a.z-b.z, a.w-b.w);
}

__global__ void pool_k(const float* __restrict__ h, const float* __restrict__ valid,
                       float* __restrict__ pooled)
{
    const int b = blockIdx.x, d = threadIdx.x;
    float s = 0.f, vs = 0.f;
#pragma unroll 8
    for (int n = 0; n < N_; n++) {
        float v = valid[b * N_ + n];
        s += h[((size_t)b * N_ + n) * D_ + d] * v;
        vs += v;
    }
    pooled[b * D_ + d] = s / vs;
}

__global__ void mlp_k(const float* __restrict__ pooled,
                      const float* __restrict__ w0, const float* __restrict__ b0,
                      const float* __restrict__ w1, const float* __restrict__ b1,
                      const float* __restrict__ w2, const float* __restrict__ b2,
                      const float* __restrict__ w3, const float* __restrict__ b3,
                      float* __restrict__ out)
{
    __shared__ float a0[128], a1[128], red[4];
    const int b = blockIdx.x, t = threadIdx.x;
    a0[t] = pooled[b * 128 + t];
    __syncthreads();
    float s = 0.f;
    for (int i = 0; i < 128; i++) s += a0[i] * w0[t*128+i];
    a1[t] = fmaxf(s + b0[t], 0.f);
    __syncthreads();
    s = 0.f;
    for (int i = 0; i < 128; i++) s += a1[i] * w1[t*128+i];
    a0[t] = fmaxf(s + b1[t], 0.f);
    __syncthreads();
    s = 0.f;
    for (int i = 0; i < 128; i++) s += a0[i] * w2[t*128+i];
    a1[t] = fmaxf(s + b2[t], 0.f);
    __syncthreads();
    float p = a1[t] * w3[t];
    for (int o = 16; o; o >>= 1) p += __shfl_xor_sync(0xFFFFFFFFu, p, o);
    if ((t & 31) == 0) red[t >> 5] = p;
    __syncthreads();
    if (t == 0) {
        float tot = red[0] + red[1] + red[2] + red[3] + b3[0];
        out[b] = 1.f / (1.f + expf(-tot));
    }
}

extern "C" void kernel_launch(void* const* d_in, const int* in_sizes, int n_in,
                              void* d_out, int out_size)
{
    const float* x       = (const float*)d_in[0];
    const float* adj1    = (const float*)d_in[1];
    const float* adj2    = (const float*)d_in[2];
    const float* valid   = (const float*)d_in[3];
    const float* embede_w= (const float*)d_in[4];
    const float* gW      = (const float*)d_in[5];
    const float* gb      = (const float*)d_in[6];
    const float* gA      = (const float*)d_in[7];
    const float* gate_w  = (const float*)d_in[8];
    const float* gate_b  = (const float*)d_in[9];
    const float* fc0_w   = (const float*)d_in[10];
    const float* fc0_b   = (const float*)d_in[11];
    const float* fc1_w   = (const float*)d_in[12];
    const float* fc1_b   = (const float*)d_in[13];
    const float* fc2_w   = (const float*)d_in[14];
    const float* fc2_b   = (const float*)d_in[15];
    const float* fc3_w   = (const float*)d_in[16];
    const float* fc3_b   = (const float*)d_in[17];
    float* out = (float*)d_out;

    float *p_h, *p_hh, *p_hA, *p_zA, *p_zC, *p_cf, *p_pool, *p_invs;
    bf16 *p_hhb, *p_hAb, *p_zb;
    float *p_ev;
    int *p_rp, *p_col, *p_mir, *p_us;
    cudaGetSymbolAddress((void**)&p_h,   g_h);
    cudaGetSymbolAddress((void**)&p_hh,  g_hh);
    cudaGetSymbolAddress((void**)&p_hA,  g_hA);
    cudaGetSymbolAddress((void**)&p_hhb, g_hhb);
    cudaGetSymbolAddress((void**)&p_hAb, g_hAb);
    cudaGetSymbolAddress((void**)&p_zb,  g_zb);
    cudaGetSymbolAddress((void**)&p_zA,  g_zA);
    cudaGetSymbolAddress((void**)&p_zC,  g_zC);
    cudaGetSymbolAddress((void**)&p_cf,  g_cf);
    cudaGetSymbolAddress((void**)&p_pool,g_pool);
    cudaGetSymbolAddress((void**)&p_ev,  g_ev);
    cudaGetSymbolAddress((void**)&p_invs,g_invs);
    cudaGetSymbolAddress((void**)&p_rp,  g_rowptr);
    cudaGetSymbolAddress((void**)&p_col, g_col);
    cudaGetSymbolAddress((void**)&p_mir, g_mir);
    cudaGetSymbolAddress((void**)&p_us,  g_us);

    const int NHOPS[4] = {1, 2, 3, 4};
    int* rp_[2]   = {p_rp,  p_rp  + (BN_ + 1)};
    int* col_[2]  = {p_col, p_col + EMAX};
    int* mir_[2]  = {p_mir, p_mir + EMAX};
    int* us_[2]   = {p_us,  p_us  + BN_};
    float* ev_[2] = {p_ev,  p_ev  + EMAX};
    bf16* zb_[2][2] = {{p_zb,                    p_zb + (size_t)BN_*D_},
                       {p_zb + 2*(size_t)BN_*D_, p_zb + 3*(size_t)BN_*D_}};

    deg_k   <<<dim3(2048,2), 256>>>(adj1, adj2, rp_[0], rp_[1]);
    scan_k  <<<2, 1024>>>(rp_[0], rp_[1]);
    fill_k  <<<dim3(2048,2), 256>>>(adj1, adj2, rp_[0], rp_[1], col_[0], col_[1]);
    mirror_k<<<dim3(2048,2), 256>>>(rp_[0], col_[0], mir_[0], us_[0],
                                    rp_[1], col_[1], mir_[1], us_[1]);

    sgemm_e_k<<<256, 256>>>(x, embede_w, p_h, D_);

    for (int k = 0; k < L_; k++) {
        const float* Wk  = gW + (size_t)k * D_ * D_;
        const float* bk  = gb + (size_t)k * D_;
        const float* Ak  = gA + (size_t)k * D_ * D_;
        const float* gwk = gate_w + (size_t)k * 2 * D_;
        const float* gbk = gate_b + k;
        const int nhop = NHOPS[k];

        hhA_k<<<256, 256>>>(p_h, Wk, Ak, bk, p_hh, p_hhb, p_hA, p_hAb);

        elog2_k<<<dim3(2048, 2), 256>>>(p_hh, p_hA, p_hhb, p_hAb,
            rp_[0], col_[0], mir_[0], us_[0], ev_[0],
            rp_[1], col_[1], mir_[1], us_[1], ev_[1]);
        stats2_k<<<4096, 256>>>(rp_[0], ev_[0], rp_[1], ev_[1], p_invs);

        // first hop: az = relu(att @ hh), both branches, one launch
        spmm_k<0><<<4096, 256>>>(rp_[0], col_[0], ev_[0],
            rp_[1], col_[1], ev_[1], p_invs, p_hhb, p_hhb,
            zb_[0][0], zb_[1][0], nullptr, nullptr, p_hh, p_cf);

        if (nhop == 1) {
            gatehop_k<true><<<2048, 256>>>(p_hh, zb_[0][0], zb_[1][0],
                                           gwk, gbk, p_cf, p_h);
        } else {
            gatehop_k<false><<<2048, 256>>>(p_hh, zb_[0][0], zb_[1][0],
                                            gwk, gbk, p_cf, nullptr);
            int cur = 0;
            for (int hp = 2; hp < nhop; hp++) {
                spmm_k<1><<<4096, 256>>>(rp_[0], col_[0], ev_[0],
                    rp_[1], col_[1], ev_[1], p_invs,
                    zb_[0][cur], zb_[1][cur],
                    zb_[0][cur^1], zb_[1][cur^1], nullptr, nullptr,
                    p_hh, p_cf);
                cur ^= 1;
            }
            spmm_k<2><<<4096, 256>>>(rp_[0], col_[0], ev_[0],
                rp_[1], col_[1], ev_[1], p_invs,
                zb_[0][cur], zb_[1][cur],
                nullptr, nullptr, p_zA, p_zC, p_hh, p_cf);
            sub_k<<<2048, 256>>>(p_zC, p_zA, p_h);
        }
    }

    pool_k<<<B_, D_>>>(p_h, valid, p_pool);
    mlp_k<<<B_, D_>>>(p_pool, fc0_w, fc0_b, fc1_w, fc1_b,
                      fc2_w, fc2_b, fc3_w, fc3_b, out);
}

// round 16
// speedup vs baseline: 1.6778x; 1.0572x over previous
#include <cuda_runtime.h>
#include <cuda_bf16.h>
#include <math.h>

#define B_ 16
#define N_ 1024
#define D_ 128
#define L_ 4
#define BN_ (B_*N_)
#define EMAX (1<<22)

typedef __nv_bfloat16 bf16;
typedef __nv_bfloat162 bf162;

__device__ __align__(128) float g_h [BN_*D_];
__device__ __align__(128) float g_hh[BN_*D_];
__device__ __align__(128) float g_hA[BN_*D_];
__device__ __align__(128) bf16  g_hhb[BN_*D_];
__device__ __align__(128) bf16  g_hAb[BN_*D_];
__device__ __align__(128) bf16  g_zb[4][BN_*D_];
__device__ __align__(128) float g_zA[BN_*D_];
__device__ __align__(128) float g_zC[BN_*D_];
__device__ __align__(128) float g_cf[2*BN_];
__device__ __align__(128) float g_pool[B_*D_];
__device__ __align__(128) int   g_rowptr[2][BN_ + 1];
__device__ __align__(128) int   g_us[2][BN_];
__device__ __align__(128) int   g_col[2][EMAX];
__device__ __align__(128) int   g_mir[2][EMAX];
__device__ __align__(128) float g_ev[2][EMAX];
__device__ __align__(128) float g_av[2][EMAX];
__device__ __align__(128) float g_invs[2*BN_];

// ---------- bf16 helpers ----------
__device__ __forceinline__ float4 ldz4(const bf16* p) {
    uint2 raw = *(const uint2*)p;
    bf162 lo = *reinterpret_cast<bf162*>(&raw.x);
    bf162 hi = *reinterpret_cast<bf162*>(&raw.y);
    float2 f0 = __bfloat1622float2(lo);
    float2 f1 = __bfloat1622float2(hi);
    return make_float4(f0.x, f0.y, f1.x, f1.y);
}
__device__ __forceinline__ void stz4(bf16* p, float4 v) {
    bf162 a = __floats2bfloat162_rn(v.x, v.y);
    bf162 b = __floats2bfloat162_rn(v.z, v.w);
    uint2 r;
    r.x = *reinterpret_cast<unsigned*>(&a);
    r.y = *reinterpret_cast<unsigned*>(&b);
    *(uint2*)p = r;
}

// ============ embede SGEMM: 64x128 tile, 4x8/thread (TRANSB) ============
__global__ void __launch_bounds__(256)
sgemm_e_k(const float* __restrict__ Ag, const float* __restrict__ Bg,
          float* __restrict__ Cg, int K)
{
    __shared__ float As[16][68];
    __shared__ float Bs[16][132];
    const int tid = threadIdx.x;
    const int tx = tid & 15, ty = tid >> 4;
    const int mbase = blockIdx.x * 64;

    const int arow  = tid >> 2;
    const int akoff = (tid & 3) * 4;
    const float* aptr = Ag + (size_t)(mbase + arow) * K + akoff;
    const int bn = tid & 127, bkh = (tid >> 7) * 8;
    const float* bptr = Bg + (size_t)bn * K + bkh;

    float acc[4][8];
#pragma unroll
    for (int i = 0; i < 4; i++)
#pragma unroll
        for (int j = 0; j < 8; j++) acc[i][j] = 0.f;

    const int nk = K >> 4;
    for (int kc = 0; kc < nk; ++kc) {
        float4 pa  = *(const float4*)(aptr + kc * 16);
        float4 pb0 = *(const float4*)(bptr + kc * 16);
        float4 pb1 = *(const float4*)(bptr + kc * 16 + 4);
        As[akoff+0][arow]=pa.x; As[akoff+1][arow]=pa.y;
        As[akoff+2][arow]=pa.z; As[akoff+3][arow]=pa.w;
        Bs[bkh+0][bn]=pb0.x; Bs[bkh+1][bn]=pb0.y;
        Bs[bkh+2][bn]=pb0.z; Bs[bkh+3][bn]=pb0.w;
        Bs[bkh+4][bn]=pb1.x; Bs[bkh+5][bn]=pb1.y;
        Bs[bkh+6][bn]=pb1.z; Bs[bkh+7][bn]=pb1.w;
        __syncthreads();
#pragma unroll
        for (int kk = 0; kk < 16; ++kk) {
            float4 av0 = *(const float4*)&As[kk][ty*4];
            float4 bv0 = *(const float4*)&Bs[kk][tx*8];
            float4 bv1 = *(const float4*)&Bs[kk][tx*8+4];
            float ar[4] = {av0.x,av0.y,av0.z,av0.w};
            float br[8] = {bv0.x,bv0.y,bv0.z,bv0.w,bv1.x,bv1.y,bv1.z,bv1.w};
#pragma unroll
            for (int i = 0; i < 4; i++)
#pragma unroll
                for (int j = 0; j < 8; j++)
                    acc[i][j] += ar[i] * br[j];
        }
        __syncthreads();
    }
    const int row0 = mbase + ty * 4;
    const int col0 = tx * 8;
#pragma unroll
    for (int i = 0; i < 4; i++) {
        float4* cp = (float4*)(Cg + (size_t)(row0 + i) * D_ + col0);
        cp[0] = make_float4(acc[i][0], acc[i][1], acc[i][2], acc[i][3]);
        cp[1] = make_float4(acc[i][4], acc[i][5], acc[i][6], acc[i][7]);
    }
}

// ===== fused: hh = h@W^T + b (f32+bf16), hA = hh@A (f32+bf16) ===
__global__ void __launch_bounds__(256)
hhA_k(const float* __restrict__ h, const float* __restrict__ W,
      const float* __restrict__ A, const float* __restrict__ bias,
      float* __restrict__ hh, bf16* __restrict__ hhb,
      float* __restrict__ hA, bf16* __restrict__ hAb)
{
    __shared__ float As[16][68];
    __shared__ float Bs[16][132];
    __shared__ float hhs[64][132];
    const int tid = threadIdx.x;
    const int tx = tid & 15, ty = tid >> 4;
    const int mbase = blockIdx.x * 64;

    const int arow  = tid >> 2;
    const int akoff = (tid & 3) * 4;
    const float* aptr = h + (size_t)(mbase + arow) * D_ + akoff;
    const int bn = tid & 127, bkh = (tid >> 7) * 8;
    const float* wptr = W + (size_t)bn * D_ + bkh;

    float acc[4][8];
#pragma unroll
    for (int i = 0; i < 4; i++)
#pragma unroll
        for (int j = 0; j < 8; j++) acc[i][j] = 0.f;

#pragma unroll 1
    for (int kc = 0; kc < 8; ++kc) {
        float4 pa  = *(const float4*)(aptr + kc * 16);
        float4 pb0 = *(const float4*)(wptr + kc * 16);
        float4 pb1 = *(const float4*)(wptr + kc * 16 + 4);
        As[akoff+0][arow]=pa.x; As[akoff+1][arow]=pa.y;
        As[akoff+2][arow]=pa.z; As[akoff+3][arow]=pa.w;
        Bs[bkh+0][bn]=pb0.x; Bs[bkh+1][bn]=pb0.y;
        Bs[bkh+2][bn]=pb0.z; Bs[bkh+3][bn]=pb0.w;
        Bs[bkh+4][bn]=pb1.x; Bs[bkh+5][bn]=pb1.y;
        Bs[bkh+6][bn]=pb1.z; Bs[bkh+7][bn]=pb1.w;
        __syncthreads();
#pragma unroll
        for (int kk = 0; kk < 16; ++kk) {
            float4 av0 = *(const float4*)&As[kk][ty*4];
            float4 bv0 = *(const float4*)&Bs[kk][tx*8];
            float4 bv1 = *(const float4*)&Bs[kk][tx*8+4];
            float ar[4] = {av0.x,av0.y,av0.z,av0.w};
            float br[8] = {bv0.x,bv0.y,bv0.z,bv0.w,bv1.x,bv1.y,bv1.z,bv1.w};
#pragma unroll
            for (int i = 0; i < 4; i++)
#pragma unroll
                for (int j = 0; j < 8; j++)
                    acc[i][j] += ar[i] * br[j];
        }
        __syncthreads();
    }

    const int row0 = ty * 4;
    const int col0 = tx * 8;
#pragma unroll
    for (int i = 0; i < 4; i++) {
        float o[8];
#pragma unroll
        for (int j = 0; j < 8; j++) {
            o[j] = acc[i][j] + bias[col0 + j];
            hhs[row0 + i][col0 + j] = o[j];
            acc[i][j] = 0.f;
        }
        const size_t go = (size_t)(mbase + row0 + i) * D_ + col0;
        *(float4*)(hh + go)     = make_float4(o[0], o[1], o[2], o[3]);
        *(float4*)(hh + go + 4) = make_float4(o[4], o[5], o[6], o[7]);
        stz4(hhb + go,     make_float4(o[0], o[1], o[2], o[3]));
        stz4(hhb + go + 4, make_float4(o[4], o[5], o[6], o[7]));
    }
    __syncthreads();

    const int bkr = tid >> 4, bcoff = (tid & 15) * 8;
#pragma unroll 1
    for (int kc = 0; kc < 8; ++kc) {
        const float* ap = A + (size_t)(kc * 16 + bkr) * D_ + bcoff;
        float4 pb0 = *(const float4*)ap;
        float4 pb1 = *(const float4*)(ap + 4);
        *(float4*)&Bs[bkr][bcoff]   = pb0;
        *(float4*)&Bs[bkr][bcoff+4] = pb1;
        __syncthreads();
#pragma unroll
        for (int kk = 0; kk < 16; ++kk) {
            float4 bv0 = *(const float4*)&Bs[kk][tx*8];
            float4 bv1 = *(const float4*)&Bs[kk][tx*8+4];
            float br[8] = {bv0.x,bv0.y,bv0.z,bv0.w,bv1.x,bv1.y,bv1.z,bv1.w};
#pragma unroll
            for (int i = 0; i < 4; i++) {
                const float a = hhs[row0 + i][kc * 16 + kk];
#pragma unroll
                for (int j = 0; j < 8; j++)
                    acc[i][j] += a * br[j];
            }
        }
        __syncthreads();
    }
#pragma unroll
    for (int i = 0; i < 4; i++) {
        const size_t go = (size_t)(mbase + row0 + i) * D_ + col0;
        *(float4*)(hA + go)     = make_float4(acc[i][0], acc[i][1], acc[i][2], acc[i][3]);
        *(float4*)(hA + go + 4) = make_float4(acc[i][4], acc[i][5], acc[i][6], acc[i][7]);
        stz4(hAb + go,     make_float4(acc[i][0], acc[i][1], acc[i][2], acc[i][3]));
        stz4(hAb + go + 4, make_float4(acc[i][4], acc[i][5], acc[i][6], acc[i][7]));
    }
}

// ============ CSR build (dual-adj via blockIdx.y) ============
__global__ void deg_k(const float* __restrict__ a0, const float* __restrict__ a1,
                      int* __restrict__ rp0, int* __restrict__ rp1)
{
    const float* adj = blockIdx.y ? a1 : a0;
    int* rp = blockIdx.y ? rp1 : rp0;
    const int wid = (blockIdx.x * blockDim.x + threadIdx.x) >> 5;
    const int lane = threadIdx.x & 31;
    if (wid >= BN_) return;
    const float* row = adj + (size_t)wid * N_;
    int c = 0;
#pragma unroll 4
    for (int k = 0; k < 32; k++) c += (row[lane + k * 32] > 0.f) ? 1 : 0;
    for (int o = 16; o; o >>= 1) c += __shfl_xor_sync(0xFFFFFFFFu, c, o);
    if (lane == 0) rp[wid + 1] = c;
}

__global__ void scan_k(int* __restrict__ rp0, int* __restrict__ rp1)
{
    int* rp = blockIdx.x ? rp1 : rp0;
    __shared__ int part[1024];
    const int t = threadIdx.x;
    int loc[16];
    int run = 0;
#pragma unroll
    for (int k = 0; k < 16; k++) { run += rp[1 + t * 16 + k]; loc[k] = run; }
    part[t] = run;
    __syncthreads();
    for (int off = 1; off < 1024; off <<= 1) {
        int v = (t >= off) ? part[t - off] : 0;
        __syncthreads();
        part[t] += v;
        __syncthreads();
    }
    const int excl = (t == 0) ? 0 : part[t - 1];
#pragma unroll
    for (int k = 0; k < 16; k++) rp[1 + t * 16 + k] = excl + loc[k];
    if (t == 0) rp[0] = 0;
}

__global__ void fill_k(const float* __restrict__ a0, const float* __restrict__ a1,
                       const int* __restrict__ rp0, const int* __restrict__ rp1,
                       int* __restrict__ col0, int* __restrict__ col1)
{
    const float* adj = blockIdx.y ? a1 : a0;
    const int* rp = blockIdx.y ? rp1 : rp0;
    int* col = blockIdx.y ? col1 : col0;
    const int wid = (blockIdx.x * blockDim.x + threadIdx.x) >> 5;
    const int lane = threadIdx.x & 31;
    if (wid >= BN_) return;
    const float* row = adj + (size_t)wid * N_;
    const int c0 = lane * 32;
    int cnt = 0;
#pragma unroll 4
    for (int k = 0; k < 32; k++) cnt += (row[c0 + k] > 0.f) ? 1 : 0;
    int inc = cnt;
    for (int off = 1; off < 32; off <<= 1) {
        int v = __shfl_up_sync(0xFFFFFFFFu, inc, off);
        if (lane >= off) inc += v;
    }
    int pos = rp[wid] + (inc - cnt);
    for (int k = 0; k < 32; k++)
        if (row[c0 + k] > 0.f) col[pos++] = c0 + k;
}

__global__ void mirror_k(const int* __restrict__ rp0, const int* __restrict__ col0,
                         int* __restrict__ mir0, int* __restrict__ us0,
                         const int* __restrict__ rp1, const int* __restrict__ col1,
                         int* __restrict__ mir1, int* __restrict__ us1)
{
    const int* rp  = blockIdx.y ? rp1  : rp0;
    const int* col = blockIdx.y ? col1 : col0;
    int* mir = blockIdx.y ? mir1 : mir0;
    int* us  = blockIdx.y ? us1  : us0;
    const int wid = (blockIdx.x * blockDim.x + threadIdx.x) >> 5;
    const int lane = threadIdx.x & 31;
    if (wid >= BN_) return;
    const int i = wid & (N_ - 1);
    const int bN = wid - i;
    const int rs = rp[wid], re = rp[wid + 1];
    for (int e = rs + lane; e < re; e += 32) {
        const int j = col[e];
        if (j == i) us[wid] = e;
        int lo = rp[bN + j], hi = rp[bN + j + 1];
        while (lo < hi) {
            int mid = (lo + hi) >> 1;
            if (col[mid] < i) lo = mid + 1; else hi = mid;
        }
        mir[e] = lo;
    }
}

// ===== edge logits: block-per-row, i-side fp32 smem, bf16 j-gather ======
__global__ void __launch_bounds__(128)
elog2_k(const float* __restrict__ hh, const float* __restrict__ hA,
        const bf16* __restrict__ hhb, const bf16* __restrict__ hAb,
        const int* __restrict__ rp0, const int* __restrict__ col0,
        const int* __restrict__ mir0, const int* __restrict__ us0,
        float* __restrict__ ev0,
        const int* __restrict__ rp1, const int* __restrict__ col1,
        const int* __restrict__ mir1, const int* __restrict__ us1,
        float* __restrict__ ev1)
{
    const int br = blockIdx.z;
    const int* rp  = br ? rp1  : rp0;
    const int* col = br ? col1 : col0;
    const int* mir = br ? mir1 : mir0;
    const int* us  = br ? us1  : us0;
    float*     ev  = br ? ev1  : ev0;

    __shared__ float shh[128], sha[128];
    const int i = blockIdx.x, b = blockIdx.y;
    const int r = b * N_ + i;
    const int t = threadIdx.x;
    shh[t] = hh[(size_t)r * D_ + t];
    sha[t] = hA[(size_t)r * D_ + t];
    __syncthreads();
    const int w = t >> 5, lane = t & 31;
    const int rs = us[r], re = rp[r + 1];
    const float4 a1 = *(const float4*)(sha + lane * 4);
    const float4 h1 = *(const float4*)(shh + lane * 4);
    for (int e = rs + w; e < re; e += 4) {
        const int j = col[e];
        const size_t jo = ((size_t)(b * N_ + j)) * D_ + lane * 4;
        const float4 h2 = ldz4(hhb + jo);
        const float4 a2 = ldz4(hAb + jo);
        float p = a1.x*h2.x + a1.y*h2.y + a1.z*h2.z + a1.w*h2.w
                + h1.x*a2.x + h1.y*a2.y + h1.z*a2.z + h1.w*a2.w;
        for (int o = 16; o; o >>= 1) p += __shfl_xor_sync(0xFFFFFFFFu, p, o);
        if (lane == 0) {
            const float x = __expf(p);
            ev[e] = x;
            ev[mir[e]] = x;
        }
    }
}

// ===== softmax denominators, both branches =====
__global__ void stats2_k(const int* __restrict__ rp0, const float* __restrict__ ev0,
                         const int* __restrict__ rp1, const float* __restrict__ ev1,
                         float* __restrict__ invs)
{
    const int u = blockIdx.x * 8 + (threadIdx.x >> 5);
    const int lane = threadIdx.x & 31;
    if (u >= 2 * BN_) return;
    const bool s1 = (u >= BN_);
    const int r = s1 ? u - BN_ : u;
    const int* rp = s1 ? rp1 : rp0;
    const float* ev = s1 ? ev1 : ev0;
    const int rs = rp[r], re = rp[r + 1];
    float s = 0.f;
    for (int e = rs + lane; e < re; e += 32) s += ev[e];
    for (int o = 16; o; o >>= 1) s += __shfl_xor_sync(0xFFFFFFFFu, s, o);
    if (lane == 0) invs[u] = 1.f / (s + (float)(N_ - (re - rs)));
}

// ===== fold column normalizer, both branches =====
__global__ void fold2_k(const int* __restrict__ rp0, const int* __restrict__ col0,
                        const float* __restrict__ ev0, float* __restrict__ av0,
                        const int* __restrict__ rp1, const int* __restrict__ col1,
                        const float* __restrict__ ev1, float* __restrict__ av1,
                        const float* __restrict__ invs)
{
    const int u = blockIdx.x * 8 + (threadIdx.x >> 5);
    const int lane = threadIdx.x & 31;
    if (u >= 2 * BN_) return;
    const bool s1 = (u >= BN_);
    const int r = s1 ? u - BN_ : u;
    const int* rp  = s1 ? rp1  : rp0;
    const int* col = s1 ? col1 : col0;
    const float* ev = s1 ? ev1 : ev0;
    float* av = s1 ? av1 : av0;
    const int ibase = (s1 ? BN_ : 0) + (r & ~(N_ - 1));
    const int rs = rp[r], re = rp[r + 1];
    for (int e = rs + lane; e < re; e += 32)
        av[e] = ev[e] * invs[ibase + col[e]];
}

// ============ SpMM: warp-per-row bf16 L2 gather, av stream ============
// Rows u in [0, 2BN): set0 if u<BN_, else set1.
// EPI 0: store relu(acc) -> bf16 (az).  EPI 1: c*hh+(1-c)*relu -> bf16.
// EPI 2: c*hh+(1-c)*relu -> fp32.
template<int EPI>
__global__ void __launch_bounds__(256)
spmm_k(const int* __restrict__ rp0, const int* __restrict__ col0,
       const float* __restrict__ av0,
       const int* __restrict__ rp1, const int* __restrict__ col1,
       const float* __restrict__ av1,
       const bf16* __restrict__ Z0, const bf16* __restrict__ Z1,
       bf16* __restrict__ outB0, bf16* __restrict__ outB1,
       float* __restrict__ outF0, float* __restrict__ outF1,
       const float* __restrict__ hh, const float* __restrict__ cf)
{
    const int u = blockIdx.x * 8 + (threadIdx.x >> 5);
    const int lane = threadIdx.x & 31;
    const bool s1 = (u >= BN_);
    const int r = s1 ? u - BN_ : u;
    const int* rp  = s1 ? rp1  : rp0;
    const int* col = s1 ? col1 : col0;
    const float* av = s1 ? av1 : av0;
    const bf16* zb = (s1 ? Z1 : Z0) + (size_t)(r & ~(N_ - 1)) * D_;
    const int rs = rp[r], re = rp[r + 1];
    const int off = lane * 4;

    float4 acc = make_float4(0.f, 0.f, 0.f, 0.f);
    int e = rs;
    for (; e + 4 <= re; e += 4) {
        const int   j0 = col[e],   j1 = col[e+1], j2 = col[e+2], j3 = col[e+3];
        const float a0 = av[e],    a1 = av[e+1],  a2 = av[e+2],  a3 = av[e+3];
        const float4 z0 = ldz4(zb + (size_t)j0 * D_ + off);
        const float4 z1 = ldz4(zb + (size_t)j1 * D_ + off);
        const float4 z2 = ldz4(zb + (size_t)j2 * D_ + off);
        const float4 z3 = ldz4(zb + (size_t)j3 * D_ + off);
        acc.x += a0*z0.x + a1*z1.x + a2*z2.x + a3*z3.x;
        acc.y += a0*z0.y + a1*z1.y + a2*z2.y + a3*z3.y;
        acc.z += a0*z0.z + a1*z1.z + a2*z2.z + a3*z3.z;
        acc.w += a0*z0.w + a1*z1.w + a2*z2.w + a3*z3.w;
    }
    for (; e < re; ++e) {
        const int j = col[e];
        const float a = av[e];
        const float4 zv = ldz4(zb + (size_t)j * D_ + off);
        acc.x += a*zv.x; acc.y += a*zv.y; acc.z += a*zv.z; acc.w += a*zv.w;
    }

    acc.x = fmaxf(acc.x, 0.f); acc.y = fmaxf(acc.y, 0.f);
    acc.z = fmaxf(acc.z, 0.f); acc.w = fmaxf(acc.w, 0.f);
    const size_t go = (size_t)r * D_ + off;

    if (EPI == 0) {
        stz4((s1 ? outB1 : outB0) + go, acc);
    } else {
        const float c = cf[u], om = 1.f - c;
        const float4 hv = *(const float4*)(hh + go);
        float4 o;
        o.x = c*hv.x + om*acc.x; o.y = c*hv.y + om*acc.y;
        o.z = c*hv.z + om*acc.z; o.w = c*hv.w + om*acc.w;
        if (EPI == 1) stz4((s1 ? outB1 : outB0) + go, o);
        else          *(float4*)((s1 ? outF1 : outF0) + go) = o;
    }
}

// ===== gate + hop1 for both branches (az post-relu in az0/az1) =====
// NH1: h_out = (c1*hh+(1-c1)*az1) - (c0*hh+(1-c0)*az0)   [fp32]
// else: az0/az1 <- bf16(c*hh+(1-c)*az) in place; cf stored.
template<bool NH1>
__global__ void __launch_bounds__(256)
gatehop_k(const float* __restrict__ hh, bf16* __restrict__ az0,
          bf16* __restrict__ az1, const float* __restrict__ gw,
          const float* __restrict__ gb, float* __restrict__ cf,
          float* __restrict__ hout)
{
    const int r = blockIdx.x * 8 + (threadIdx.x >> 5);
    const int lane = threadIdx.x & 31;
    if (r >= BN_) return;
    const size_t o = (size_t)r * D_ + lane * 4;
    const float4 hv = *(const float4*)(hh + o);
    const float4 z0 = ldz4(az0 + o);
    const float4 z1 = ldz4(az1 + o);
    const float4 g1 = *(const float4*)(gw + lane * 4);
    const float4 g2 = *(const float4*)(gw + D_ + lane * 4);
    const float t = hv.x*g1.x + hv.y*g1.y + hv.z*g1.z + hv.w*g1.w;
    float s0 = t + z0.x*g2.x + z0.y*g2.y + z0.z*g2.z + z0.w*g2.w;
    float s1 = t + z1.x*g2.x + z1.y*g2.y + z1.z*g2.z + z1.w*g2.w;
#pragma unroll
    for (int off = 16; off; off >>= 1) {
        s0 += __shfl_xor_sync(0xFFFFFFFFu, s0, off);
        s1 += __shfl_xor_sync(0xFFFFFFFFu, s1, off);
    }
    const float gbv = gb[0];
    const float c0 = 1.f / (1.f + __expf(-(s0 + gbv)));
    const float c1 = 1.f / (1.f + __expf(-(s1 + gbv)));
    if (NH1) {
        float4 ov;
        ov.x = (c1*hv.x + (1.f-c1)*z1.x) - (c0*hv.x + (1.f-c0)*z0.x);
        ov.y = (c1*hv.y + (1.f-c1)*z1.y) - (c0*hv.y + (1.f-c0)*z0.y);
        ov.z = (c1*hv.z + (1.f-c1)*z1.z) - (c0*hv.z + (1.f-c0)*z0.z);
        ov.w = (c1*hv.w + (1.f-c1)*z1.w) - (c0*hv.w + (1.f-c0)*z0.w);
        *(float4*)(hout + o) = ov;
    } else {
        float4 w0, w1;
        w0.x = c0*hv.x + (1.f-c0)*z0.x; w0.y = c0*hv.y + (1.f-c0)*z0.y;
        w0.z = c0*hv.z + (1.f-c0)*z0.z; w0.w = c0*hv.w + (1.f-c0)*z0.w;
        w1.x = c1*hv.x + (1.f-c1)*z1.x; w1.y = c1*hv.y + (1.f-c1)*z1.y;
        w1.z = c1*hv.z + (1.f-c1)*z1.z; w1.w = c1*hv.w + (1.f-c1)*z1.w;
        stz4(az0 + o, w0);
        stz4(az1 + o, w1);
        if (lane == 0) { cf[r] = c0; cf[BN_ + r] = c1; }
    }
}

// ============ tail ============
__global__ void sub_k(const float* __restrict__ z2, const float* __restrict__ z1,
                      float* __restrict__ o)
{
    const size_t i = (size_t)blockIdx.x * blockDim.x + threadIdx.x;
    float4 a = ((const float4*)z2)[i];
    float4 b = ((const float4*)z1)[i];
    ((float4*)o)[i] = make_float4(a.x-b.x, a.y-b.y, a.z-b.z, a.w-b.w);
}

__global__ void pool_k(const float* __restrict__ h, const float* __restrict__ valid,
                       float* __restrict__ pooled)
{
    const int b = blockIdx.x, d = threadIdx.x;
    float s = 0.f, vs = 0.f;
#pragma unroll 8
    for (int n = 0; n < N_; n++) {
        float v = valid[b * N_ + n];
        s += h[((size_t)b * N_ + n) * D_ + d] * v;
        vs += v;
    }
    pooled[b * D_ + d] = s / vs;
}

__global__ void mlp_k(const float* __restrict__ pooled,
                      const float* __restrict__ w0, const float* __restrict__ b0,
                      const float* __restrict__ w1, const float* __restrict__ b1,
                      const float* __restrict__ w2, const float* __restrict__ b2,
                      const float* __restrict__ w3, const float* __restrict__ b3,
                      float* __restrict__ out)
{
    __shared__ float a0[128], a1[128], red[4];
    const int b = blockIdx.x, t = threadIdx.x;
    a0[t] = pooled[b * 128 + t];
    __syncthreads();
    float s = 0.f;
    for (int i = 0; i < 128; i++) s += a0[i] * w0[t*128+i];
    a1[t] = fmaxf(s + b0[t], 0.f);
    __syncthreads();
    s = 0.f;
    for (int i = 0; i < 128; i++) s += a1[i] * w1[t*128+i];
    a0[t] = fmaxf(s + b1[t], 0.f);
    __syncthreads();
    s = 0.f;
    for (int i = 0; i < 128; i++) s += a0[i] * w2[t*128+i];
    a1[t] = fmaxf(s + b2[t], 0.f);
    __syncthreads();
    float p = a1[t] * w3[t];
    for (int o = 16; o; o >>= 1) p += __shfl_xor_sync(0xFFFFFFFFu, p, o);
    if ((t & 31) == 0) red[t >> 5] = p;
    __syncthreads();
    if (t == 0) {
        float tot = red[0] + red[1] + red[2] + red[3] + b3[0];
        out[b] = 1.f / (1.f + expf(-tot));
    }
}

extern "C" void kernel_launch(void* const* d_in, const int* in_sizes, int n_in,
                              void* d_out, int out_size)
{
    const float* x       = (const float*)d_in[0];
    const float* adj1    = (const float*)d_in[1];
    const float* adj2    = (const float*)d_in[2];
    const float* valid   = (const float*)d_in[3];
    const float* embede_w= (const float*)d_in[4];
    const float* gW      = (const float*)d_in[5];
    const float* gb      = (const float*)d_in[6];
    const float* gA      = (const float*)d_in[7];
    const float* gate_w  = (const float*)d_in[8];
    const float* gate_b  = (const float*)d_in[9];
    const float* fc0_w   = (const float*)d_in[10];
    const float* fc0_b   = (const float*)d_in[11];
    const float* fc1_w   = (const float*)d_in[12];
    const float* fc1_b   = (const float*)d_in[13];
    const float* fc2_w   = (const float*)d_in[14];
    const float* fc2_b   = (const float*)d_in[15];
    const float* fc3_w   = (const float*)d_in[16];
    const float* fc3_b   = (const float*)d_in[17];
    float* out = (float*)d_out;

    float *p_h, *p_hh, *p_hA, *p_zA, *p_zC, *p_cf, *p_pool, *p_invs;
    bf16 *p_hhb, *p_hAb, *p_zb;
    float *p_ev, *p_av;
    int *p_rp, *p_col, *p_mir, *p_us;
    cudaGetSymbolAddress((void**)&p_h,   g_h);
    cudaGetSymbolAddress((void**)&p_hh,  g_hh);
    cudaGetSymbolAddress((void**)&p_hA,  g_hA);
    cudaGetSymbolAddress((void**)&p_hhb, g_hhb);
    cudaGetSymbolAddress((void**)&p_hAb, g_hAb);
    cudaGetSymbolAddress((void**)&p_zb,  g_zb);
    cudaGetSymbolAddress((void**)&p_zA,  g_zA);
    cudaGetSymbolAddress((void**)&p_zC,  g_zC);
    cudaGetSymbolAddress((void**)&p_cf,  g_cf);
    cudaGetSymbolAddress((void**)&p_pool,g_pool);
    cudaGetSymbolAddress((void**)&p_ev,  g_ev);
    cudaGetSymbolAddress((void**)&p_av,  g_av);
    cudaGetSymbolAddress((void**)&p_invs,g_invs);
    cudaGetSymbolAddress((void**)&p_rp,  g_rowptr);
    cudaGetSymbolAddress((void**)&p_col, g_col);
    cudaGetSymbolAddress((void**)&p_mir, g_mir);
    cudaGetSymbolAddress((void**)&p_us,  g_us);

    const int NHOPS[4] = {1, 2, 3, 4};
    int* rp_[2]   = {p_rp,  p_rp  + (BN_ + 1)};
    int* col_[2]  = {p_col, p_col + EMAX};
    int* mir_[2]  = {p_mir, p_mir + EMAX};
    int* us_[2]   = {p_us,  p_us  + BN_};
    float* ev_[2] = {p_ev,  p_ev  + EMAX};
    float* av_[2] = {p_av,  p_av  + EMAX};
    bf16* zb_[2][2] = {{p_zb,                    p_zb + (size_t)BN_*D_},
                       {p_zb + 2*(size_t)BN_*D_, p_zb + 3*(size_t)BN_*D_}};

    deg_k   <<<dim3(2048,2), 256>>>(adj1, adj2, rp_[0], rp_[1]);
    scan_k  <<<2, 1024>>>(rp_[0], rp_[1]);
    fill_k  <<<dim3(2048,2), 256>>>(adj1, adj2, rp_[0], rp_[1], col_[0], col_[1]);
    mirror_k<<<dim3(2048,2), 256>>>(rp_[0], col_[0], mir_[0], us_[0],
                                    rp_[1], col_[1], mir_[1], us_[1]);

    sgemm_e_k<<<256, 256>>>(x, embede_w, p_h, D_);

    for (int k = 0; k < L_; k++) {
        const float* Wk  = gW + (size_t)k * D_ * D_;
        const float* bk  = gb + (size_t)k * D_;
        const float* Ak  = gA + (size_t)k * D_ * D_;
        const float* gwk = gate_w + (size_t)k * 2 * D_;
        const float* gbk = gate_b + k;
        const int nhop = NHOPS[k];

        hhA_k<<<256, 256>>>(p_h, Wk, Ak, bk, p_hh, p_hhb, p_hA, p_hAb);

        elog2_k<<<dim3(N_, B_, 2), 128>>>(p_hh, p_hA, p_hhb, p_hAb,
            rp_[0], col_[0], mir_[0], us_[0], ev_[0],
            rp_[1], col_[1], mir_[1], us_[1], ev_[1]);
        stats2_k<<<4096, 256>>>(rp_[0], ev_[0], rp_[1], ev_[1], p_invs);
        fold2_k <<<4096, 256>>>(rp_[0], col_[0], ev_[0], av_[0],
                                rp_[1], col_[1], ev_[1], av_[1], p_invs);

        // first hop: az = relu(att @ hh), both branches, one launch
        spmm_k<0><<<4096, 256>>>(rp_[0], col_[0], av_[0],
            rp_[1], col_[1], av_[1], p_hhb, p_hhb,
            zb_[0][0], zb_[1][0], nullptr, nullptr, p_hh, p_cf);

        if (nhop == 1) {
            gatehop_k<true><<<2048, 256>>>(p_hh, zb_[0][0], zb_[1][0],
                                           gwk, gbk, p_cf, p_h);
        } else {
            gatehop_k<false><<<2048, 256>>>(p_hh, zb_[0][0], zb_[1][0],
                                            gwk, gbk, p_cf, nullptr);
            int cur = 0;
            for (int hp = 2; hp < nhop; hp++) {
                spmm_k<1><<<4096, 256>>>(rp_[0], col_[0], av_[0],
                    rp_[1], col_[1], av_[1],
                    zb_[0][cur], zb_[1][cur],
                    zb_[0][cur^1], zb_[1][cur^1], nullptr, nullptr,
                    p_hh, p_cf);
                cur ^= 1;
            }
            spmm_k<2><<<4096, 256>>>(rp_[0], col_[0], av_[0],
                rp_[1], col_[1], av_[1],
                zb_[0][cur], zb_[1][cur],
                nullptr, nullptr, p_zA, p_zC, p_hh, p_cf);
            sub_k<<<2048, 256>>>(p_zC, p_zA, p_h);
        }
    }

    pool_k<<<B_, D_>>>(p_h, valid, p_pool);
    mlp_k<<<B_, D_>>>(p_pool, fc0_w, fc0_b, fc1_w, fc1_b,
                      fc2_w, fc2_b, fc3_w, fc3_b, out);
}